// round 12
// baseline (speedup 1.0000x reference)
#include <cuda_runtime.h>
#include <cuda_fp16.h>
#include <math.h>
#include <stdint.h>

#define N_TOK 2048
#define D_DIM 1024
#define H_DIM 4096
#define E_NUM 8
#define R_DIM 16
#define LSCALE 2.0f
#define NSLOT (2*N_TOK)

// ---------------- scratch ----------------
__device__ __half g_acth[NSLOT * H_DIM];
__device__ float  g_t1[NSLOT * R_DIM];
__device__ float  g_t2[NSLOT * R_DIM];
__device__ int    g_sel[NSLOT];
__device__ float  g_wt[NSLOT];
__device__ int g_cnt[E_NUM];
__device__ int g_off[E_NUM];
__device__ int g_pos[E_NUM];
__device__ int g_list[NSLOT];
__device__ __half g_xh[N_TOK * D_DIM];
__device__ __half g_w1h[H_DIM * D_DIM];
__device__ __half g_w2h[D_DIM * H_DIM];

// ---------------- f32 -> f16 conversion (block 0 also zeroes expert counts) ----------------
__global__ void cvt_f32_f16(const float* __restrict__ in, __half* __restrict__ out, int n) {
    if (blockIdx.x == 0 && threadIdx.x < E_NUM) g_cnt[threadIdx.x] = 0;
    int i = (blockIdx.x * 256 + threadIdx.x) * 8;
    if (i >= n) return;
    float4 v0 = *(const float4*)(in + i);
    float4 v1 = *(const float4*)(in + i + 4);
    __half2 h[4];
    h[0] = __floats2half2_rn(v0.x, v0.y);
    h[1] = __floats2half2_rn(v0.z, v0.w);
    h[2] = __floats2half2_rn(v1.x, v1.y);
    h[3] = __floats2half2_rn(v1.z, v1.w);
    *(uint4*)(out + i) = *(uint4*)h;
}

// ---------------- router (fused expert count) ----------------
__global__ void router_kernel(const float* __restrict__ x, const float* __restrict__ gate) {
    int t = blockIdx.x;
    int warp = threadIdx.x >> 5, lane = threadIdx.x & 31;
    __shared__ float logits[E_NUM];
    const float4* xr = (const float4*)(x + (size_t)t * D_DIM);
    const float4* gr = (const float4*)(gate + (size_t)warp * D_DIM);
    float s = 0.f;
    for (int i = lane; i < D_DIM / 4; i += 32) {
        float4 a = xr[i], b = gr[i];
        s += a.x * b.x + a.y * b.y + a.z * b.z + a.w * b.w;
    }
    #pragma unroll
    for (int o = 16; o; o >>= 1) s += __shfl_xor_sync(0xffffffffu, s, o);
    if (lane == 0) logits[warp] = s;
    __syncthreads();
    if (threadIdx.x == 0) {
        float best = -1e30f; int i0 = 0;
        #pragma unroll
        for (int e = 0; e < E_NUM; e++) if (logits[e] > best) { best = logits[e]; i0 = e; }
        float best2 = -1e30f; int i1 = 0;
        #pragma unroll
        for (int e = 0; e < E_NUM; e++) if (e != i0 && logits[e] > best2) { best2 = logits[e]; i1 = e; }
        float p1 = expf(best2 - best);
        float inv = 1.f / (1.f + p1);
        g_sel[t * 2 + 0] = i0; g_sel[t * 2 + 1] = i1;
        g_wt[t * 2 + 0] = inv; g_wt[t * 2 + 1] = p1 * inv;
        atomicAdd(&g_cnt[i0], 1);
        atomicAdd(&g_cnt[i1], 1);
    }
}

// ---------------- dispatch ----------------
__global__ void dispatch_prefix() {
    if (threadIdx.x == 0) {
        int o = 0;
        for (int e = 0; e < E_NUM; e++) { g_off[e] = o; g_pos[e] = o; o += g_cnt[e]; }
    }
}
__global__ void dispatch_scatter() {
    int i = blockIdx.x * 256 + threadIdx.x;
    if (i < NSLOT) {
        int e = g_sel[i];
        int pos = atomicAdd(&g_pos[e], 1);
        g_list[pos] = i;
    }
}

// ---------------- shared GEMM machinery (R11-proven mainloop) ----------------
__device__ __forceinline__ void mma_f16(float* c, const unsigned* a, const unsigned* b) {
    asm volatile(
        "mma.sync.aligned.m16n8k16.row.col.f32.f16.f16.f32 "
        "{%0,%1,%2,%3}, {%4,%5,%6,%7}, {%8,%9}, {%0,%1,%2,%3};"
        : "+f"(c[0]), "+f"(c[1]), "+f"(c[2]), "+f"(c[3])
        : "r"(a[0]), "r"(a[1]), "r"(a[2]), "r"(a[3]), "r"(b[0]), "r"(b[1]));
}
__device__ __forceinline__ void ldsm_x4(unsigned* r, uint32_t addr) {
    asm volatile("ldmatrix.sync.aligned.m8n8.x4.shared.b16 {%0,%1,%2,%3}, [%4];"
        : "=r"(r[0]), "=r"(r[1]), "=r"(r[2]), "=r"(r[3]) : "r"(addr));
}
__device__ __forceinline__ uint32_t smem_u32(const void* p) {
    uint32_t a;
    asm("{ .reg .u64 t; cvta.to.shared.u64 t, %1; cvt.u32.u64 %0, t; }" : "=r"(a) : "l"(p));
    return a;
}
__device__ __forceinline__ void cp_async16(uint32_t dst, const void* src) {
    asm volatile("cp.async.ca.shared.global [%0], [%1], 16;" :: "r"(dst), "l"(src));
}
#define CP_COMMIT() asm volatile("cp.async.commit_group;" ::: "memory")
#define CP_WAIT(n)  asm volatile("cp.async.wait_group %0;" :: "n"(n) : "memory")

#define GSTRH 40
#define GHTILE (128 * GSTRH)
#define GSTAGEB (2 * GHTILE * 2)
#define GSMEM (3 * GSTAGEB)

// Mainloop as a macro-like inline: computes acc[2][8][4] for tile (bm, bn).
// (structured as a device function operating on caller locals via references)
struct GemmCtx {
    uint32_t sb;
    int bm, bn, lane, wid, wm, wn, g, tg;
    const char *Ap0, *Ap1, *Bp0, *Bp1;
    uint32_t oA0, oA1, oB0, oB1;
    uint32_t laA[2], laB[4];
};

__device__ __forceinline__ void gemm_init(GemmCtx& cx, const __half* A, const __half* B,
                                          int K, uint32_t sb) {
    int tid = threadIdx.x;
    cx.sb = sb;
    cx.bm = blockIdx.y * 128; cx.bn = blockIdx.x * 128;
    cx.lane = tid & 31; cx.wid = tid >> 5;
    cx.wm = (cx.wid >> 1) * 32; cx.wn = (cx.wid & 1) * 64;
    cx.g = cx.lane >> 2; cx.tg = cx.lane & 3;
    int row0 = (tid * 2) >> 2,     q0 = (tid * 2) & 3;
    int row1 = (tid * 2 + 1) >> 2, q1 = (tid * 2 + 1) & 3;
    cx.Ap0 = (const char*)(A + (size_t)(cx.bm + row0) * K + q0 * 8);
    cx.Ap1 = (const char*)(A + (size_t)(cx.bm + row1) * K + q1 * 8);
    cx.Bp0 = (const char*)(B + (size_t)(cx.bn + row0) * K + q0 * 8);
    cx.Bp1 = (const char*)(B + (size_t)(cx.bn + row1) * K + q1 * 8);
    cx.oA0 = (uint32_t)(row0 * GSTRH + q0 * 8) * 2;
    cx.oA1 = (uint32_t)(row1 * GSTRH + q1 * 8) * 2;
    cx.oB0 = (uint32_t)GHTILE * 2 + cx.oA0;
    cx.oB1 = (uint32_t)GHTILE * 2 + cx.oA1;
    #pragma unroll
    for (int mt = 0; mt < 2; mt++)
        cx.laA[mt] = (uint32_t)((cx.wm + mt * 16 + (cx.lane & 15)) * GSTRH +
                                ((cx.lane & 16) ? 8 : 0)) * 2;
    #pragma unroll
    for (int p = 0; p < 4; p++)
        cx.laB[p] = (uint32_t)GHTILE * 2 +
                    (uint32_t)((cx.wn + 16 * p + (cx.lane & 7) + ((cx.lane & 16) ? 8 : 0)) * GSTRH +
                               ((cx.lane & 8) ? 8 : 0)) * 2;
}

__device__ __forceinline__ void gemm_mainloop(GemmCtx& cx, float acc[2][8][4], int K) {
    #pragma unroll
    for (int mt = 0; mt < 2; mt++)
        #pragma unroll
        for (int nt = 0; nt < 8; nt++)
            #pragma unroll
            for (int i = 0; i < 4; i++) acc[mt][nt][i] = 0.f;
    int ntk = K >> 5;
    #pragma unroll
    for (int s = 0; s < 2; s++) {
        uint32_t st = cx.sb + s * GSTAGEB;
        size_t ko = (size_t)s * 64;
        cp_async16(st + cx.oA0, cx.Ap0 + ko); cp_async16(st + cx.oA1, cx.Ap1 + ko);
        cp_async16(st + cx.oB0, cx.Bp0 + ko); cp_async16(st + cx.oB1, cx.Bp1 + ko);
        CP_COMMIT();
    }
    for (int kt = 0; kt < ntk; kt++) {
        int b = kt % 3;
        if (kt + 1 < ntk) { CP_WAIT(1); } else { CP_WAIT(0); }
        __syncthreads();
        if (kt + 2 < ntk) {
            int s = (kt + 2) % 3;
            uint32_t st = cx.sb + s * GSTAGEB;
            size_t ko = (size_t)(kt + 2) * 64;
            cp_async16(st + cx.oA0, cx.Ap0 + ko); cp_async16(st + cx.oA1, cx.Ap1 + ko);
            cp_async16(st + cx.oB0, cx.Bp0 + ko); cp_async16(st + cx.oB1, cx.Bp1 + ko);
            CP_COMMIT();
        }
        uint32_t stg = cx.sb + b * GSTAGEB;
        #pragma unroll
        for (int kg = 0; kg < 2; kg++) {
            uint32_t kofs = kg * 32;
            unsigned av[2][4], bv[4][4];
            #pragma unroll
            for (int mt = 0; mt < 2; mt++)
                ldsm_x4(av[mt], stg + cx.laA[mt] + kofs);
            #pragma unroll
            for (int p = 0; p < 4; p++)
                ldsm_x4(bv[p], stg + cx.laB[p] + kofs);
            #pragma unroll
            for (int mt = 0; mt < 2; mt++)
                #pragma unroll
                for (int nt = 0; nt < 8; nt++)
                    mma_f16(acc[mt][nt], av[mt], &bv[nt >> 1][(nt & 1) * 2]);
        }
    }
}

__device__ __forceinline__ float dot16(const float* a, const float4* b4) {
    float s = 0.f;
    #pragma unroll
    for (int q = 0; q < 4; q++) {
        float4 b = b4[q];
        s += a[q * 4 + 0] * b.x + a[q * 4 + 1] * b.y + a[q * 4 + 2] * b.z + a[q * 4 + 3] * b.w;
    }
    return s;
}
__device__ __forceinline__ float fast_silu(float v) {
    return __fdividef(v, 1.f + __expf(-v));
}

// ---------------- GEMM1 + bias + LoRA-up + silu -> acth (both slots per token) ----------------
__global__ __launch_bounds__(256, 2)
void gemm1_act_kernel(const __half* __restrict__ A, const __half* __restrict__ B,
                      const float* __restrict__ b1, const float* __restrict__ B1mat,
                      int M, int N, int K) {
    extern __shared__ __half smh[];
    GemmCtx cx;
    gemm_init(cx, A, B, K, smem_u32(smh));
    float acc[2][8][4];
    gemm_mainloop(cx, acc, K);

    #pragma unroll
    for (int mt = 0; mt < 2; mt++) {
        #pragma unroll
        for (int rh = 0; rh < 2; rh++) {
            int tok = cx.bm + cx.wm + mt * 16 + cx.g + rh * 8;
            int p0 = tok * 2, p1 = tok * 2 + 1;
            int e0 = g_sel[p0], e1 = g_sel[p1];
            const float* t1a = g_t1 + p0 * R_DIM;
            const float* t1b = g_t1 + p1 * R_DIM;
            __half* o0 = g_acth + (size_t)p0 * H_DIM;
            __half* o1 = g_acth + (size_t)p1 * H_DIM;
            #pragma unroll
            for (int nt = 0; nt < 8; nt++) {
                int c0 = cx.bn + cx.wn + nt * 8 + 2 * cx.tg;
                float a0[2], a1[2];
                #pragma unroll
                for (int j = 0; j < 2; j++) {
                    int h = c0 + j;
                    float base = acc[mt][nt][rh * 2 + j] + b1[h];
                    float l0 = dot16(t1a, (const float4*)(B1mat + ((size_t)e0 * H_DIM + h) * R_DIM));
                    float l1 = dot16(t1b, (const float4*)(B1mat + ((size_t)e1 * H_DIM + h) * R_DIM));
                    a0[j] = fast_silu(base + LSCALE * l0);
                    a1[j] = fast_silu(base + LSCALE * l1);
                }
                *(__half2*)(o0 + c0) = __floats2half2_rn(a0[0], a0[1]);
                *(__half2*)(o1 + c0) = __floats2half2_rn(a1[0], a1[1]);
            }
        }
    }
}

// ---------------- GEMM2 + bias + LoRA-up + weighted token combine -> out ----------------
__global__ __launch_bounds__(256, 2)
void gemm2_combine_kernel(const __half* __restrict__ A, const __half* __restrict__ B,
                          const float* __restrict__ b2, const float* __restrict__ B2mat,
                          float* __restrict__ out, int M, int N, int K) {
    extern __shared__ __half smh[];
    GemmCtx cx;
    gemm_init(cx, A, B, K, smem_u32(smh));
    float acc[2][8][4];
    gemm_mainloop(cx, acc, K);

    #pragma unroll
    for (int mt = 0; mt < 2; mt++) {
        #pragma unroll
        for (int rh = 0; rh < 2; rh++) {
            int p = cx.bm + cx.wm + mt * 16 + cx.g + rh * 8;  // slot; parity = parity(g)
            int e = g_sel[p];
            float w = g_wt[p];
            const float* t2v = g_t2 + p * R_DIM;
            float* orow = out + (size_t)(p >> 1) * D_DIM;
            #pragma unroll
            for (int nt = 0; nt < 8; nt++) {
                int c0 = cx.bn + cx.wn + nt * 8 + 2 * cx.tg;
                float wv[2];
                #pragma unroll
                for (int j = 0; j < 2; j++) {
                    int d = c0 + j;
                    float base = acc[mt][nt][rh * 2 + j] + b2[d];
                    float l = dot16(t2v, (const float4*)(B2mat + ((size_t)e * D_DIM + d) * R_DIM));
                    wv[j] = w * (base + LSCALE * l);
                }
                // partner slot (p^1) lives at lane^4
                float pv0 = __shfl_xor_sync(0xffffffffu, wv[0], 4);
                float pv1 = __shfl_xor_sync(0xffffffffu, wv[1], 4);
                if (!(cx.g & 1)) {
                    *(float2*)(orow + c0) = make_float2(wv[0] + pv0, wv[1] + pv1);
                }
            }
        }
    }
}

// ---------------- grouped rank-16 down-projection (fp16 input rows) ----------------
#define GL_G 32
#define GL_KC 128
__global__ __launch_bounds__(256)
void lora_in_grouped_h(const __half* __restrict__ X, const float* __restrict__ Amat,
                       float* __restrict__ Tout, int K, int tok_row) {
    int e = blockIdx.y;
    int n_e = g_cnt[e];
    int base = blockIdx.x * GL_G;
    if (base >= n_e) return;
    __shared__ float As[R_DIM][GL_KC];
    __shared__ int sl[GL_G];
    int tid = threadIdx.x, lane = tid & 31, w = tid >> 5;
    if (tid < GL_G) {
        int j = base + tid;
        sl[tid] = (j < n_e) ? g_list[g_off[e] + j] : -1;
    }
    __syncthreads();
    int p[4];
    const __half* xr[4];
    #pragma unroll
    for (int s = 0; s < 4; s++) {
        p[s] = sl[w * 4 + s];
        int row = (p[s] < 0) ? 0 : (tok_row ? (p[s] >> 1) : p[s]);
        xr[s] = X + (size_t)row * K;
    }
    float acc[4][R_DIM];
    #pragma unroll
    for (int s = 0; s < 4; s++)
        #pragma unroll
        for (int r = 0; r < R_DIM; r++) acc[s][r] = 0.f;

    const float* Ae = Amat + (size_t)e * R_DIM * K;
    for (int k0 = 0; k0 < K; k0 += GL_KC) {
        __syncthreads();
        #pragma unroll
        for (int l = 0; l < 2; l++) {
            int i = tid * 2 + l;
            int r = i >> 5, kq = i & 31;
            *(float4*)&As[r][kq * 4] = *(const float4*)(Ae + (size_t)r * K + k0 + kq * 4);
        }
        __syncthreads();
        float4 xv[4];
        #pragma unroll
        for (int s = 0; s < 4; s++) {
            __half2 h01 = *(const __half2*)(xr[s] + k0 + lane * 4);
            __half2 h23 = *(const __half2*)(xr[s] + k0 + lane * 4 + 2);
            float2 f01 = __half22float2(h01);
            float2 f23 = __half22float2(h23);
            xv[s] = make_float4(f01.x, f01.y, f23.x, f23.y);
        }
        #pragma unroll
        for (int r = 0; r < R_DIM; r++) {
            float4 a4 = *(const float4*)&As[r][lane * 4];
            #pragma unroll
            for (int s = 0; s < 4; s++)
                acc[s][r] += xv[s].x * a4.x + xv[s].y * a4.y + xv[s].z * a4.z + xv[s].w * a4.w;
        }
    }
    #pragma unroll
    for (int s = 0; s < 4; s++) {
        #pragma unroll
        for (int r = 0; r < R_DIM; r++) {
            float v = acc[s][r];
            v += __shfl_xor_sync(0xffffffffu, v, 16);
            v += __shfl_xor_sync(0xffffffffu, v, 8);
            v += __shfl_xor_sync(0xffffffffu, v, 4);
            v += __shfl_xor_sync(0xffffffffu, v, 2);
            v += __shfl_xor_sync(0xffffffffu, v, 1);
            if (lane == 0 && p[s] >= 0) Tout[p[s] * R_DIM + r] = v;
        }
    }
}

// ---------------- launch ----------------
extern "C" void kernel_launch(void* const* d_in, const int* in_sizes, int n_in,
                              void* d_out, int out_size) {
    const float* x    = (const float*)d_in[0];
    const float* gate = (const float*)d_in[1];
    const float* W1   = (const float*)d_in[2];
    const float* b1   = (const float*)d_in[3];
    const float* W2   = (const float*)d_in[4];
    const float* b2   = (const float*)d_in[5];
    const float* A1   = (const float*)d_in[6];
    const float* B1   = (const float*)d_in[7];
    const float* A2   = (const float*)d_in[8];
    const float* B2   = (const float*)d_in[9];
    float* out = (float*)d_out;

    float *p_t1, *p_t2;
    __half *p_xh, *p_w1h, *p_w2h, *p_acth;
    cudaGetSymbolAddress((void**)&p_t1,   g_t1);
    cudaGetSymbolAddress((void**)&p_t2,   g_t2);
    cudaGetSymbolAddress((void**)&p_xh,   g_xh);
    cudaGetSymbolAddress((void**)&p_w1h,  g_w1h);
    cudaGetSymbolAddress((void**)&p_w2h,  g_w2h);
    cudaGetSymbolAddress((void**)&p_acth, g_acth);

    cudaFuncSetAttribute(gemm1_act_kernel,
                         cudaFuncAttributeMaxDynamicSharedMemorySize, GSMEM);
    cudaFuncSetAttribute(gemm2_combine_kernel,
                         cudaFuncAttributeMaxDynamicSharedMemorySize, GSMEM);

    // 0. fp16 copies of GEMM inputs (first also zeroes expert counts)
    cvt_f32_f16<<<(N_TOK * D_DIM) / 2048, 256>>>(x, p_xh, N_TOK * D_DIM);
    cvt_f32_f16<<<(H_DIM * D_DIM) / 2048, 256>>>(W1, p_w1h, H_DIM * D_DIM);
    cvt_f32_f16<<<(D_DIM * H_DIM) / 2048, 256>>>(W2, p_w2h, D_DIM * H_DIM);

    // 1. router (fused expert count)
    router_kernel<<<N_TOK, 256>>>(x, gate);

    // 2. dispatch
    dispatch_prefix<<<1, 32>>>();
    dispatch_scatter<<<NSLOT / 256, 256>>>();

    // 3. t1 = x @ A1[e]^T (needed by GEMM1 epilogue)
    lora_in_grouped_h<<<dim3(NSLOT / GL_G, E_NUM), 256>>>(p_xh, A1, p_t1, D_DIM, 1);

    // 4. acth = silu(X@W1^T + b1 + LSCALE * t1 @ B1[e]^T)  (fused)
    {
        dim3 grid(H_DIM / 128, N_TOK / 128);
        gemm1_act_kernel<<<grid, 256, GSMEM>>>(p_xh, p_w1h, b1, B1, N_TOK, H_DIM, D_DIM);
    }

    // 5. t2 = a @ A2[e]^T
    lora_in_grouped_h<<<dim3(NSLOT / GL_G, E_NUM), 256>>>(p_acth, A2, p_t2, H_DIM, 0);

    // 6. out = sum_k w_k * (a@W2^T + b2 + LSCALE * t2 @ B2[e]^T)  (fused)
    {
        dim3 grid(D_DIM / 128, NSLOT / 128);
        gemm2_combine_kernel<<<grid, 256, GSMEM>>>(p_acth, p_w2h, b2, B2, out, NSLOT, D_DIM, H_DIM);
    }
}

// round 13
// speedup vs baseline: 1.2976x; 1.2976x over previous
#include <cuda_runtime.h>
#include <cuda_fp16.h>
#include <math.h>
#include <stdint.h>

#define N_TOK 2048
#define D_DIM 1024
#define H_DIM 4096
#define E_NUM 8
#define R_DIM 16
#define LSCALE 2.0f
#define NSLOT (2*N_TOK)

// ---------------- scratch ----------------
__device__ __half g_commonh[N_TOK * H_DIM];
__device__ __half g_acth[NSLOT * H_DIM];
__device__ float  g_t1[NSLOT * R_DIM];
__device__ float  g_t2[NSLOT * R_DIM];
__device__ int    g_sel[NSLOT];
__device__ float  g_wt[NSLOT];
__device__ int g_cnt[E_NUM];
__device__ int g_off[E_NUM];
__device__ int g_pos[E_NUM];
__device__ int g_list[NSLOT];
__device__ __half g_xh[N_TOK * D_DIM];
__device__ __half g_w1h[H_DIM * D_DIM];
__device__ __half g_w2h[D_DIM * H_DIM];

// ---------------- f32 -> f16 conversion (block 0 also zeroes expert counts) ----------------
__global__ void cvt_f32_f16(const float* __restrict__ in, __half* __restrict__ out, int n) {
    if (blockIdx.x == 0 && threadIdx.x < E_NUM) g_cnt[threadIdx.x] = 0;
    int i = (blockIdx.x * 256 + threadIdx.x) * 8;
    if (i >= n) return;
    float4 v0 = *(const float4*)(in + i);
    float4 v1 = *(const float4*)(in + i + 4);
    __half2 h[4];
    h[0] = __floats2half2_rn(v0.x, v0.y);
    h[1] = __floats2half2_rn(v0.z, v0.w);
    h[2] = __floats2half2_rn(v1.x, v1.y);
    h[3] = __floats2half2_rn(v1.z, v1.w);
    *(uint4*)(out + i) = *(uint4*)h;
}

// ---------------- router (fused expert count) ----------------
__global__ void router_kernel(const float* __restrict__ x, const float* __restrict__ gate) {
    int t = blockIdx.x;
    int warp = threadIdx.x >> 5, lane = threadIdx.x & 31;
    __shared__ float logits[E_NUM];
    const float4* xr = (const float4*)(x + (size_t)t * D_DIM);
    const float4* gr = (const float4*)(gate + (size_t)warp * D_DIM);
    float s = 0.f;
    for (int i = lane; i < D_DIM / 4; i += 32) {
        float4 a = xr[i], b = gr[i];
        s += a.x * b.x + a.y * b.y + a.z * b.z + a.w * b.w;
    }
    #pragma unroll
    for (int o = 16; o; o >>= 1) s += __shfl_xor_sync(0xffffffffu, s, o);
    if (lane == 0) logits[warp] = s;
    __syncthreads();
    if (threadIdx.x == 0) {
        float best = -1e30f; int i0 = 0;
        #pragma unroll
        for (int e = 0; e < E_NUM; e++) if (logits[e] > best) { best = logits[e]; i0 = e; }
        float best2 = -1e30f; int i1 = 0;
        #pragma unroll
        for (int e = 0; e < E_NUM; e++) if (e != i0 && logits[e] > best2) { best2 = logits[e]; i1 = e; }
        float p1 = expf(best2 - best);
        float inv = 1.f / (1.f + p1);
        g_sel[t * 2 + 0] = i0; g_sel[t * 2 + 1] = i1;
        g_wt[t * 2 + 0] = inv; g_wt[t * 2 + 1] = p1 * inv;
        atomicAdd(&g_cnt[i0], 1);
        atomicAdd(&g_cnt[i1], 1);
    }
}

// ---------------- dispatch ----------------
__global__ void dispatch_prefix() {
    if (threadIdx.x == 0) {
        int o = 0;
        for (int e = 0; e < E_NUM; e++) { g_off[e] = o; g_pos[e] = o; o += g_cnt[e]; }
    }
}
__global__ void dispatch_scatter() {
    int i = blockIdx.x * 256 + threadIdx.x;
    if (i < NSLOT) {
        int e = g_sel[i];
        int pos = atomicAdd(&g_pos[e], 1);
        g_list[pos] = i;
    }
}

// ---------------- GEMM machinery ----------------
__device__ __forceinline__ void mma_f16(float* c, const unsigned* a, const unsigned* b) {
    asm volatile(
        "mma.sync.aligned.m16n8k16.row.col.f32.f16.f16.f32 "
        "{%0,%1,%2,%3}, {%4,%5,%6,%7}, {%8,%9}, {%0,%1,%2,%3};"
        : "+f"(c[0]), "+f"(c[1]), "+f"(c[2]), "+f"(c[3])
        : "r"(a[0]), "r"(a[1]), "r"(a[2]), "r"(a[3]), "r"(b[0]), "r"(b[1]));
}
__device__ __forceinline__ void ldsm_x4(unsigned* r, uint32_t addr) {
    asm volatile("ldmatrix.sync.aligned.m8n8.x4.shared.b16 {%0,%1,%2,%3}, [%4];"
        : "=r"(r[0]), "=r"(r[1]), "=r"(r[2]), "=r"(r[3]) : "r"(addr));
}
__device__ __forceinline__ uint32_t smem_u32(const void* p) {
    uint32_t a;
    asm("{ .reg .u64 t; cvta.to.shared.u64 t, %1; cvt.u32.u64 %0, t; }" : "=r"(a) : "l"(p));
    return a;
}
__device__ __forceinline__ void cp_async16(uint32_t dst, const void* src) {
    asm volatile("cp.async.ca.shared.global [%0], [%1], 16;" :: "r"(dst), "l"(src));
}
#define CP_COMMIT() asm volatile("cp.async.commit_group;" ::: "memory")
#define CP_WAIT(n)  asm volatile("cp.async.wait_group %0;" :: "n"(n) : "memory")

__device__ __forceinline__ void store2(float* p, float x, float y) { p[0] = x; p[1] = y; }
__device__ __forceinline__ void store2(__half* p, float x, float y) {
    *(__half2*)p = __floats2half2_rn(x, y);
}

#define GSTRH 40
#define GHTILE (128 * GSTRH)
#define GSTAGEB (2 * GHTILE * 2)
#define GSMEM (3 * GSTAGEB)

// common mainloop prelude macro (R11-identical)
#define GEMM_PRELUDE(A, B, K)                                                            \
    uint32_t sb = smem_u32(smh);                                                         \
    int bm = blockIdx.y * 128, bn = blockIdx.x * 128;                                    \
    int tid = threadIdx.x;                                                               \
    int lane = tid & 31, wid = tid >> 5;                                                 \
    int wm = (wid >> 1) * 32, wn = (wid & 1) * 64;                                       \
    int g = lane >> 2, tg = lane & 3;                                                    \
    int row0 = (tid * 2) >> 2,     q0 = (tid * 2) & 3;                                   \
    int row1 = (tid * 2 + 1) >> 2, q1 = (tid * 2 + 1) & 3;                               \
    const char* Ap0 = (const char*)(A + (size_t)(bm + row0) * K + q0 * 8);               \
    const char* Ap1 = (const char*)(A + (size_t)(bm + row1) * K + q1 * 8);               \
    const char* Bp0 = (const char*)(B + (size_t)(bn + row0) * K + q0 * 8);               \
    const char* Bp1 = (const char*)(B + (size_t)(bn + row1) * K + q1 * 8);               \
    uint32_t oA0 = (uint32_t)(row0 * GSTRH + q0 * 8) * 2;                                \
    uint32_t oA1 = (uint32_t)(row1 * GSTRH + q1 * 8) * 2;                                \
    uint32_t oB0 = (uint32_t)GHTILE * 2 + oA0;                                           \
    uint32_t oB1 = (uint32_t)GHTILE * 2 + oA1;                                           \
    uint32_t laA[2];                                                                     \
    _Pragma("unroll")                                                                    \
    for (int mt = 0; mt < 2; mt++)                                                       \
        laA[mt] = (uint32_t)((wm + mt * 16 + (lane & 15)) * GSTRH +                      \
                             ((lane & 16) ? 8 : 0)) * 2;                                 \
    uint32_t laB[4];                                                                     \
    _Pragma("unroll")                                                                    \
    for (int p = 0; p < 4; p++)                                                          \
        laB[p] = (uint32_t)GHTILE * 2 +                                                  \
                 (uint32_t)((wn + 16 * p + (lane & 7) + ((lane & 16) ? 8 : 0)) * GSTRH + \
                            ((lane & 8) ? 8 : 0)) * 2;                                   \
    float acc[2][8][4];                                                                  \
    _Pragma("unroll")                                                                    \
    for (int mt = 0; mt < 2; mt++)                                                       \
        _Pragma("unroll")                                                                \
        for (int nt = 0; nt < 8; nt++)                                                   \
            _Pragma("unroll")                                                            \
            for (int i = 0; i < 4; i++) acc[mt][nt][i] = 0.f;                            \
    int ntk = K >> 5;                                                                    \
    _Pragma("unroll")                                                                    \
    for (int s = 0; s < 2; s++) {                                                        \
        uint32_t st = sb + s * GSTAGEB;                                                  \
        size_t ko = (size_t)s * 64;                                                      \
        cp_async16(st + oA0, Ap0 + ko); cp_async16(st + oA1, Ap1 + ko);                  \
        cp_async16(st + oB0, Bp0 + ko); cp_async16(st + oB1, Bp1 + ko);                  \
        CP_COMMIT();                                                                     \
    }                                                                                    \
    for (int kt = 0; kt < ntk; kt++) {                                                   \
        int b = kt % 3;                                                                  \
        if (kt + 1 < ntk) { CP_WAIT(1); } else { CP_WAIT(0); }                           \
        __syncthreads();                                                                 \
        if (kt + 2 < ntk) {                                                              \
            int s = (kt + 2) % 3;                                                        \
            uint32_t st = sb + s * GSTAGEB;                                              \
            size_t ko = (size_t)(kt + 2) * 64;                                           \
            cp_async16(st + oA0, Ap0 + ko); cp_async16(st + oA1, Ap1 + ko);              \
            cp_async16(st + oB0, Bp0 + ko); cp_async16(st + oB1, Bp1 + ko);              \
            CP_COMMIT();                                                                 \
        }                                                                                \
        uint32_t stg = sb + b * GSTAGEB;                                                 \
        _Pragma("unroll")                                                                \
        for (int kg = 0; kg < 2; kg++) {                                                 \
            uint32_t kofs = kg * 32;                                                     \
            unsigned av[2][4], bv[4][4];                                                 \
            _Pragma("unroll")                                                            \
            for (int mt = 0; mt < 2; mt++)                                               \
                ldsm_x4(av[mt], stg + laA[mt] + kofs);                                   \
            _Pragma("unroll")                                                            \
            for (int p = 0; p < 4; p++)                                                  \
                ldsm_x4(bv[p], stg + laB[p] + kofs);                                     \
            _Pragma("unroll")                                                            \
            for (int mt = 0; mt < 2; mt++)                                               \
                _Pragma("unroll")                                                        \
                for (int nt = 0; nt < 8; nt++)                                           \
                    mma_f16(acc[mt][nt], av[mt], &bv[nt >> 1][(nt & 1) * 2]);            \
        }                                                                                \
    }

// ---------------- plain GEMM (for GEMM1 -> commonh) ----------------
template <typename CT>
__global__ __launch_bounds__(256)
void gemm_f16_kernel(const __half* __restrict__ A, const __half* __restrict__ B,
                     CT* __restrict__ C, int M, int N, int K) {
    extern __shared__ __half smh[];
    GEMM_PRELUDE(A, B, K)
    #pragma unroll
    for (int mt = 0; mt < 2; mt++) {
        #pragma unroll
        for (int nt = 0; nt < 8; nt++) {
            int r0 = bm + wm + mt * 16 + g;
            int c0 = bn + wn + nt * 8 + 2 * tg;
            store2(C + (size_t)r0 * N + c0,       acc[mt][nt][0], acc[mt][nt][1]);
            store2(C + (size_t)(r0 + 8) * N + c0, acc[mt][nt][2], acc[mt][nt][3]);
        }
    }
}

// ---------------- GEMM2 + bias + LoRA-up + weighted combine (smem-staged epilogue) ----------------
__global__ __launch_bounds__(256)
void gemm2_combine_kernel(const __half* __restrict__ A, const __half* __restrict__ B,
                          const float* __restrict__ b2, const float* __restrict__ B2mat,
                          float* __restrict__ out, int M, int N, int K) {
    extern __shared__ __half smh[];
    GEMM_PRELUDE(A, B, K)

    // ---- epilogue: stage operands in smem (reuse pipeline buffers) ----
    __syncthreads();
    __half* B2s = smh;                               // [E_NUM][128][16] fp16 = 32KB
    float*  t2s = (float*)(smh + 16384);             // [128][16] = 8KB
    float*  wts = (float*)(smh + 16384 + 4096);      // [128]
    int*    sels = (int*)(smh + 16384 + 4096 + 256); // [128]
    float*  b2s = (float*)(smh + 16384 + 4096 + 512);// [128]

    for (int idx = tid; idx < E_NUM * 128; idx += 256) {
        int e = idx >> 7, dl = idx & 127;
        const float4* src = (const float4*)(B2mat + ((size_t)e * D_DIM + bn + dl) * R_DIM);
        float4 v0 = src[0], v1 = src[1], v2 = src[2], v3 = src[3];
        __half2 hv[8];
        hv[0] = __floats2half2_rn(v0.x, v0.y); hv[1] = __floats2half2_rn(v0.z, v0.w);
        hv[2] = __floats2half2_rn(v1.x, v1.y); hv[3] = __floats2half2_rn(v1.z, v1.w);
        hv[4] = __floats2half2_rn(v2.x, v2.y); hv[5] = __floats2half2_rn(v2.z, v2.w);
        hv[6] = __floats2half2_rn(v3.x, v3.y); hv[7] = __floats2half2_rn(v3.z, v3.w);
        uint4* dst = (uint4*)(B2s + idx * 16);
        dst[0] = ((uint4*)hv)[0];
        dst[1] = ((uint4*)hv)[1];
    }
    for (int idx = tid; idx < 512; idx += 256)
        ((float4*)t2s)[idx] = *(const float4*)(g_t2 + (size_t)bm * R_DIM + idx * 4);
    if (tid < 128) {
        wts[tid] = g_wt[bm + tid];
        sels[tid] = g_sel[bm + tid];
        b2s[tid] = b2[bn + tid];
    }
    __syncthreads();

    #pragma unroll
    for (int mt = 0; mt < 2; mt++) {
        #pragma unroll
        for (int rh = 0; rh < 2; rh++) {
            int lp = wm + mt * 16 + g + rh * 8;   // local slot; parity = g&1
            int e = sels[lp];
            float w = wts[lp];
            const float* tv = t2s + lp * R_DIM;
            float* orow = out + (size_t)((bm + lp) >> 1) * D_DIM;
            #pragma unroll
            for (int nt = 0; nt < 8; nt++) {
                int c0 = wn + nt * 8 + 2 * tg;
                float wv[2];
                #pragma unroll
                for (int j = 0; j < 2; j++) {
                    int dl = c0 + j;
                    const uint4* brow = (const uint4*)(B2s + ((size_t)e * 128 + dl) * 16);
                    uint4 u0 = brow[0], u1 = brow[1];
                    const __half2* hp = (const __half2*)&u0;
                    const __half2* hq = (const __half2*)&u1;
                    float dot = 0.f;
                    #pragma unroll
                    for (int q = 0; q < 4; q++) {
                        float2 f = __half22float2(hp[q]);
                        dot += tv[q * 2] * f.x + tv[q * 2 + 1] * f.y;
                    }
                    #pragma unroll
                    for (int q = 0; q < 4; q++) {
                        float2 f = __half22float2(hq[q]);
                        dot += tv[8 + q * 2] * f.x + tv[8 + q * 2 + 1] * f.y;
                    }
                    wv[j] = w * (acc[mt][nt][rh * 2 + j] + b2s[dl] + LSCALE * dot);
                }
                float pv0 = __shfl_xor_sync(0xffffffffu, wv[0], 4);
                float pv1 = __shfl_xor_sync(0xffffffffu, wv[1], 4);
                if (!(g & 1))
                    *(float2*)(orow + bn + c0) = make_float2(wv[0] + pv0, wv[1] + pv1);
            }
        }
    }
}

// ---------------- grouped rank-16 down-projection (fp16 input rows) ----------------
#define GL_G 32
#define GL_KC 128
__global__ __launch_bounds__(256)
void lora_in_grouped_h(const __half* __restrict__ X, const float* __restrict__ Amat,
                       float* __restrict__ Tout, int K, int tok_row) {
    int e = blockIdx.y;
    int n_e = g_cnt[e];
    int base = blockIdx.x * GL_G;
    if (base >= n_e) return;
    __shared__ float As[R_DIM][GL_KC];
    __shared__ int sl[GL_G];
    int tid = threadIdx.x, lane = tid & 31, w = tid >> 5;
    if (tid < GL_G) {
        int j = base + tid;
        sl[tid] = (j < n_e) ? g_list[g_off[e] + j] : -1;
    }
    __syncthreads();
    int p[4];
    const __half* xr[4];
    #pragma unroll
    for (int s = 0; s < 4; s++) {
        p[s] = sl[w * 4 + s];
        int row = (p[s] < 0) ? 0 : (tok_row ? (p[s] >> 1) : p[s]);
        xr[s] = X + (size_t)row * K;
    }
    float acc[4][R_DIM];
    #pragma unroll
    for (int s = 0; s < 4; s++)
        #pragma unroll
        for (int r = 0; r < R_DIM; r++) acc[s][r] = 0.f;

    const float* Ae = Amat + (size_t)e * R_DIM * K;
    for (int k0 = 0; k0 < K; k0 += GL_KC) {
        __syncthreads();
        #pragma unroll
        for (int l = 0; l < 2; l++) {
            int i = tid * 2 + l;
            int r = i >> 5, kq = i & 31;
            *(float4*)&As[r][kq * 4] = *(const float4*)(Ae + (size_t)r * K + k0 + kq * 4);
        }
        __syncthreads();
        float4 xv[4];
        #pragma unroll
        for (int s = 0; s < 4; s++) {
            __half2 h01 = *(const __half2*)(xr[s] + k0 + lane * 4);
            __half2 h23 = *(const __half2*)(xr[s] + k0 + lane * 4 + 2);
            float2 f01 = __half22float2(h01);
            float2 f23 = __half22float2(h23);
            xv[s] = make_float4(f01.x, f01.y, f23.x, f23.y);
        }
        #pragma unroll
        for (int r = 0; r < R_DIM; r++) {
            float4 a4 = *(const float4*)&As[r][lane * 4];
            #pragma unroll
            for (int s = 0; s < 4; s++)
                acc[s][r] += xv[s].x * a4.x + xv[s].y * a4.y + xv[s].z * a4.z + xv[s].w * a4.w;
        }
    }
    #pragma unroll
    for (int s = 0; s < 4; s++) {
        #pragma unroll
        for (int r = 0; r < R_DIM; r++) {
            float v = acc[s][r];
            v += __shfl_xor_sync(0xffffffffu, v, 16);
            v += __shfl_xor_sync(0xffffffffu, v, 8);
            v += __shfl_xor_sync(0xffffffffu, v, 4);
            v += __shfl_xor_sync(0xffffffffu, v, 2);
            v += __shfl_xor_sync(0xffffffffu, v, 1);
            if (lane == 0 && p[s] >= 0) Tout[p[s] * R_DIM + r] = v;
        }
    }
}

// ---------------- grouped fc1 epilogue (half in/out, fast silu) ----------------
#define GA_G 16
__global__ __launch_bounds__(256)
void act_grouped(const float* __restrict__ B1mat, const float* __restrict__ b1) {
    int e = blockIdx.y;
    int n_e = g_cnt[e];
    int base = blockIdx.x * GA_G;
    if (base >= n_e) return;
    int cnt = min(GA_G, n_e - base);
    __shared__ float t1s[GA_G][R_DIM];
    __shared__ int sl[GA_G];
    int tid = threadIdx.x;
    if (tid < GA_G) sl[tid] = (tid < cnt) ? g_list[g_off[e] + base + tid] : -1;
    __syncthreads();
    if (tid < GA_G * R_DIM) {
        int s = tid >> 4, r = tid & 15;
        int ps = sl[s];
        t1s[s][r] = (ps >= 0) ? g_t1[ps * R_DIM + r] : 0.f;
    }
    __syncthreads();
    const float* B1e = B1mat + (size_t)e * H_DIM * R_DIM;
    for (int h = tid; h < H_DIM; h += 256) {
        const float4* br = (const float4*)(B1e + (size_t)h * R_DIM);
        float4 v0 = br[0], v1 = br[1], v2 = br[2], v3 = br[3];
        float bb = b1[h];
        #pragma unroll
        for (int s = 0; s < GA_G; s++) {
            int ps = sl[s];
            if (ps >= 0) {
                float lor = v0.x * t1s[s][0]  + v0.y * t1s[s][1]  + v0.z * t1s[s][2]  + v0.w * t1s[s][3]
                          + v1.x * t1s[s][4]  + v1.y * t1s[s][5]  + v1.z * t1s[s][6]  + v1.w * t1s[s][7]
                          + v2.x * t1s[s][8]  + v2.y * t1s[s][9]  + v2.z * t1s[s][10] + v2.w * t1s[s][11]
                          + v3.x * t1s[s][12] + v3.y * t1s[s][13] + v3.z * t1s[s][14] + v3.w * t1s[s][15];
                float val = __half2float(g_commonh[(size_t)(ps >> 1) * H_DIM + h]) + bb + LSCALE * lor;
                float a = __fdividef(val, 1.f + __expf(-val));
                g_acth[(size_t)ps * H_DIM + h] = __float2half_rn(a);
            }
        }
    }
}

// ---------------- launch ----------------
extern "C" void kernel_launch(void* const* d_in, const int* in_sizes, int n_in,
                              void* d_out, int out_size) {
    const float* x    = (const float*)d_in[0];
    const float* gate = (const float*)d_in[1];
    const float* W1   = (const float*)d_in[2];
    const float* b1   = (const float*)d_in[3];
    const float* W2   = (const float*)d_in[4];
    const float* b2   = (const float*)d_in[5];
    const float* A1   = (const float*)d_in[6];
    const float* B1   = (const float*)d_in[7];
    const float* A2   = (const float*)d_in[8];
    const float* B2   = (const float*)d_in[9];
    float* out = (float*)d_out;

    float *p_t1, *p_t2;
    __half *p_xh, *p_w1h, *p_w2h, *p_acth, *p_commonh;
    cudaGetSymbolAddress((void**)&p_t1,      g_t1);
    cudaGetSymbolAddress((void**)&p_t2,      g_t2);
    cudaGetSymbolAddress((void**)&p_xh,      g_xh);
    cudaGetSymbolAddress((void**)&p_w1h,     g_w1h);
    cudaGetSymbolAddress((void**)&p_w2h,     g_w2h);
    cudaGetSymbolAddress((void**)&p_acth,    g_acth);
    cudaGetSymbolAddress((void**)&p_commonh, g_commonh);

    cudaFuncSetAttribute(gemm_f16_kernel<__half>,
                         cudaFuncAttributeMaxDynamicSharedMemorySize, GSMEM);
    cudaFuncSetAttribute(gemm2_combine_kernel,
                         cudaFuncAttributeMaxDynamicSharedMemorySize, GSMEM);

    // 0. fp16 copies of GEMM inputs (first also zeroes expert counts)
    cvt_f32_f16<<<(N_TOK * D_DIM) / 2048, 256>>>(x, p_xh, N_TOK * D_DIM);
    cvt_f32_f16<<<(H_DIM * D_DIM) / 2048, 256>>>(W1, p_w1h, H_DIM * D_DIM);
    cvt_f32_f16<<<(D_DIM * H_DIM) / 2048, 256>>>(W2, p_w2h, D_DIM * H_DIM);

    // 1. router (fused expert count)
    router_kernel<<<N_TOK, 256>>>(x, gate);

    // 2. dispatch
    dispatch_prefix<<<1, 32>>>();
    dispatch_scatter<<<NSLOT / 256, 256>>>();

    // 3. common_fc1 = X @ W1^T -> fp16
    {
        dim3 grid(H_DIM / 128, N_TOK / 128);
        gemm_f16_kernel<__half><<<grid, 256, GSMEM>>>(p_xh, p_w1h, p_commonh, N_TOK, H_DIM, D_DIM);
    }

    // 4. t1 = x @ A1[e]^T
    lora_in_grouped_h<<<dim3(NSLOT / GL_G, E_NUM), 256>>>(p_xh, A1, p_t1, D_DIM, 1);

    // 5. a = silu(common + b1 + scale * t1 @ B1[e]^T) -> fp16
    act_grouped<<<dim3(NSLOT / GA_G, E_NUM), 256>>>(B1, b1);

    // 6. t2 = a @ A2[e]^T
    lora_in_grouped_h<<<dim3(NSLOT / GL_G, E_NUM), 256>>>(p_acth, A2, p_t2, H_DIM, 0);

    // 7. out = sum_k w_k * (a@W2^T + b2 + LSCALE * t2 @ B2[e]^T)  (fused, smem-staged)
    {
        dim3 grid(D_DIM / 128, NSLOT / 128);
        gemm2_combine_kernel<<<grid, 256, GSMEM>>>(p_acth, p_w2h, b2, B2, out, NSLOT, D_DIM, H_DIM);
    }
}

// round 14
// speedup vs baseline: 1.4284x; 1.1008x over previous
#include <cuda_runtime.h>
#include <cuda_fp16.h>
#include <math.h>
#include <stdint.h>

#define N_TOK 2048
#define D_DIM 1024
#define H_DIM 4096
#define E_NUM 8
#define R_DIM 16
#define LSCALE 2.0f
#define NSLOT (2*N_TOK)

// ---------------- scratch ----------------
__device__ __half g_acth[NSLOT * H_DIM];
__device__ float  g_t1[NSLOT * R_DIM];
__device__ float  g_t2[NSLOT * R_DIM];
__device__ int    g_sel[NSLOT];
__device__ float  g_wt[NSLOT];
__device__ int g_cnt[E_NUM];
__device__ int g_off[E_NUM];
__device__ int g_pos[E_NUM];
__device__ int g_list[NSLOT];
__device__ __half g_xh[N_TOK * D_DIM];
__device__ __half g_w1h[H_DIM * D_DIM];
__device__ __half g_w2h[D_DIM * H_DIM];

// ---------------- f32 -> f16 conversion (block 0 also zeroes expert counts) ----------------
__global__ void cvt_f32_f16(const float* __restrict__ in, __half* __restrict__ out, int n) {
    if (blockIdx.x == 0 && threadIdx.x < E_NUM) g_cnt[threadIdx.x] = 0;
    int i = (blockIdx.x * 256 + threadIdx.x) * 8;
    if (i >= n) return;
    float4 v0 = *(const float4*)(in + i);
    float4 v1 = *(const float4*)(in + i + 4);
    __half2 h[4];
    h[0] = __floats2half2_rn(v0.x, v0.y);
    h[1] = __floats2half2_rn(v0.z, v0.w);
    h[2] = __floats2half2_rn(v1.x, v1.y);
    h[3] = __floats2half2_rn(v1.z, v1.w);
    *(uint4*)(out + i) = *(uint4*)h;
}

// ---------------- router (fused expert count) ----------------
__global__ void router_kernel(const float* __restrict__ x, const float* __restrict__ gate) {
    int t = blockIdx.x;
    int warp = threadIdx.x >> 5, lane = threadIdx.x & 31;
    __shared__ float logits[E_NUM];
    const float4* xr = (const float4*)(x + (size_t)t * D_DIM);
    const float4* gr = (const float4*)(gate + (size_t)warp * D_DIM);
    float s = 0.f;
    for (int i = lane; i < D_DIM / 4; i += 32) {
        float4 a = xr[i], b = gr[i];
        s += a.x * b.x + a.y * b.y + a.z * b.z + a.w * b.w;
    }
    #pragma unroll
    for (int o = 16; o; o >>= 1) s += __shfl_xor_sync(0xffffffffu, s, o);
    if (lane == 0) logits[warp] = s;
    __syncthreads();
    if (threadIdx.x == 0) {
        float best = -1e30f; int i0 = 0;
        #pragma unroll
        for (int e = 0; e < E_NUM; e++) if (logits[e] > best) { best = logits[e]; i0 = e; }
        float best2 = -1e30f; int i1 = 0;
        #pragma unroll
        for (int e = 0; e < E_NUM; e++) if (e != i0 && logits[e] > best2) { best2 = logits[e]; i1 = e; }
        float p1 = expf(best2 - best);
        float inv = 1.f / (1.f + p1);
        g_sel[t * 2 + 0] = i0; g_sel[t * 2 + 1] = i1;
        g_wt[t * 2 + 0] = inv; g_wt[t * 2 + 1] = p1 * inv;
        atomicAdd(&g_cnt[i0], 1);
        atomicAdd(&g_cnt[i1], 1);
    }
}

// ---------------- dispatch ----------------
__global__ void dispatch_prefix() {
    if (threadIdx.x == 0) {
        int o = 0;
        for (int e = 0; e < E_NUM; e++) { g_off[e] = o; g_pos[e] = o; o += g_cnt[e]; }
    }
}
__global__ void dispatch_scatter() {
    int i = blockIdx.x * 256 + threadIdx.x;
    if (i < NSLOT) {
        int e = g_sel[i];
        int pos = atomicAdd(&g_pos[e], 1);
        g_list[pos] = i;
    }
}

// ---------------- GEMM machinery ----------------
__device__ __forceinline__ void mma_f16(float* c, const unsigned* a, const unsigned* b) {
    asm volatile(
        "mma.sync.aligned.m16n8k16.row.col.f32.f16.f16.f32 "
        "{%0,%1,%2,%3}, {%4,%5,%6,%7}, {%8,%9}, {%0,%1,%2,%3};"
        : "+f"(c[0]), "+f"(c[1]), "+f"(c[2]), "+f"(c[3])
        : "r"(a[0]), "r"(a[1]), "r"(a[2]), "r"(a[3]), "r"(b[0]), "r"(b[1]));
}
__device__ __forceinline__ void ldsm_x4(unsigned* r, uint32_t addr) {
    asm volatile("ldmatrix.sync.aligned.m8n8.x4.shared.b16 {%0,%1,%2,%3}, [%4];"
        : "=r"(r[0]), "=r"(r[1]), "=r"(r[2]), "=r"(r[3]) : "r"(addr));
}
__device__ __forceinline__ uint32_t smem_u32(const void* p) {
    uint32_t a;
    asm("{ .reg .u64 t; cvta.to.shared.u64 t, %1; cvt.u32.u64 %0, t; }" : "=r"(a) : "l"(p));
    return a;
}
__device__ __forceinline__ void cp_async16(uint32_t dst, const void* src) {
    asm volatile("cp.async.ca.shared.global [%0], [%1], 16;" :: "r"(dst), "l"(src));
}
#define CP_COMMIT() asm volatile("cp.async.commit_group;" ::: "memory")
#define CP_WAIT(n)  asm volatile("cp.async.wait_group %0;" :: "n"(n) : "memory")

#define GSTRH 40
#define GHTILE (128 * GSTRH)
#define GSTAGEB (2 * GHTILE * 2)
#define GSMEM (3 * GSTAGEB)

// common mainloop prelude macro (R11-identical)
#define GEMM_PRELUDE(A, B, K)                                                            \
    uint32_t sb = smem_u32(smh);                                                         \
    int bm = blockIdx.y * 128, bn = blockIdx.x * 128;                                    \
    int tid = threadIdx.x;                                                               \
    int lane = tid & 31, wid = tid >> 5;                                                 \
    int wm = (wid >> 1) * 32, wn = (wid & 1) * 64;                                       \
    int g = lane >> 2, tg = lane & 3;                                                    \
    int row0 = (tid * 2) >> 2,     q0 = (tid * 2) & 3;                                   \
    int row1 = (tid * 2 + 1) >> 2, q1 = (tid * 2 + 1) & 3;                               \
    const char* Ap0 = (const char*)(A + (size_t)(bm + row0) * K + q0 * 8);               \
    const char* Ap1 = (const char*)(A + (size_t)(bm + row1) * K + q1 * 8);               \
    const char* Bp0 = (const char*)(B + (size_t)(bn + row0) * K + q0 * 8);               \
    const char* Bp1 = (const char*)(B + (size_t)(bn + row1) * K + q1 * 8);               \
    uint32_t oA0 = (uint32_t)(row0 * GSTRH + q0 * 8) * 2;                                \
    uint32_t oA1 = (uint32_t)(row1 * GSTRH + q1 * 8) * 2;                                \
    uint32_t oB0 = (uint32_t)GHTILE * 2 + oA0;                                           \
    uint32_t oB1 = (uint32_t)GHTILE * 2 + oA1;                                           \
    uint32_t laA[2];                                                                     \
    _Pragma("unroll")                                                                    \
    for (int mt = 0; mt < 2; mt++)                                                       \
        laA[mt] = (uint32_t)((wm + mt * 16 + (lane & 15)) * GSTRH +                      \
                             ((lane & 16) ? 8 : 0)) * 2;                                 \
    uint32_t laB[4];                                                                     \
    _Pragma("unroll")                                                                    \
    for (int p = 0; p < 4; p++)                                                          \
        laB[p] = (uint32_t)GHTILE * 2 +                                                  \
                 (uint32_t)((wn + 16 * p + (lane & 7) + ((lane & 16) ? 8 : 0)) * GSTRH + \
                            ((lane & 8) ? 8 : 0)) * 2;                                   \
    float acc[2][8][4];                                                                  \
    _Pragma("unroll")                                                                    \
    for (int mt = 0; mt < 2; mt++)                                                       \
        _Pragma("unroll")                                                                \
        for (int nt = 0; nt < 8; nt++)                                                   \
            _Pragma("unroll")                                                            \
            for (int i = 0; i < 4; i++) acc[mt][nt][i] = 0.f;                            \
    int ntk = K >> 5;                                                                    \
    _Pragma("unroll")                                                                    \
    for (int s = 0; s < 2; s++) {                                                        \
        uint32_t st = sb + s * GSTAGEB;                                                  \
        size_t ko = (size_t)s * 64;                                                      \
        cp_async16(st + oA0, Ap0 + ko); cp_async16(st + oA1, Ap1 + ko);                  \
        cp_async16(st + oB0, Bp0 + ko); cp_async16(st + oB1, Bp1 + ko);                  \
        CP_COMMIT();                                                                     \
    }                                                                                    \
    for (int kt = 0; kt < ntk; kt++) {                                                   \
        int b = kt % 3;                                                                  \
        if (kt + 1 < ntk) { CP_WAIT(1); } else { CP_WAIT(0); }                           \
        __syncthreads();                                                                 \
        if (kt + 2 < ntk) {                                                              \
            int s = (kt + 2) % 3;                                                        \
            uint32_t st = sb + s * GSTAGEB;                                              \
            size_t ko = (size_t)(kt + 2) * 64;                                           \
            cp_async16(st + oA0, Ap0 + ko); cp_async16(st + oA1, Ap1 + ko);              \
            cp_async16(st + oB0, Bp0 + ko); cp_async16(st + oB1, Bp1 + ko);              \
            CP_COMMIT();                                                                 \
        }                                                                                \
        uint32_t stg = sb + b * GSTAGEB;                                                 \
        _Pragma("unroll")                                                                \
        for (int kg = 0; kg < 2; kg++) {                                                 \
            uint32_t kofs = kg * 32;                                                     \
            unsigned av[2][4], bv[4][4];                                                 \
            _Pragma("unroll")                                                            \
            for (int mt = 0; mt < 2; mt++)                                               \
                ldsm_x4(av[mt], stg + laA[mt] + kofs);                                   \
            _Pragma("unroll")                                                            \
            for (int p = 0; p < 4; p++)                                                  \
                ldsm_x4(bv[p], stg + laB[p] + kofs);                                     \
            _Pragma("unroll")                                                            \
            for (int mt = 0; mt < 2; mt++)                                               \
                _Pragma("unroll")                                                        \
                for (int nt = 0; nt < 8; nt++)                                           \
                    mma_f16(acc[mt][nt], av[mt], &bv[nt >> 1][(nt & 1) * 2]);            \
        }                                                                                \
    }

// smem-resident rank-16 dot: t (fp32[16]) . brow (fp16[16])
__device__ __forceinline__ float dot16h(const float* tv, const __half* brow) {
    const uint4* bp = (const uint4*)brow;
    uint4 u0 = bp[0], u1 = bp[1];
    const __half2* hp = (const __half2*)&u0;
    const __half2* hq = (const __half2*)&u1;
    float dot = 0.f;
    #pragma unroll
    for (int q = 0; q < 4; q++) {
        float2 f = __half22float2(hp[q]);
        dot += tv[q * 2] * f.x + tv[q * 2 + 1] * f.y;
    }
    #pragma unroll
    for (int q = 0; q < 4; q++) {
        float2 f = __half22float2(hq[q]);
        dot += tv[8 + q * 2] * f.x + tv[8 + q * 2 + 1] * f.y;
    }
    return dot;
}
__device__ __forceinline__ float fast_silu(float v) {
    return __fdividef(v, 1.f + __expf(-v));
}

// ---------------- GEMM1 + bias + LoRA-up + silu -> acth (smem-staged epilogue) ----------------
__global__ __launch_bounds__(256)
void gemm1_act_kernel(const __half* __restrict__ A, const __half* __restrict__ B,
                      const float* __restrict__ b1, const float* __restrict__ B1mat,
                      int M, int N, int K) {
    extern __shared__ __half smh[];
    GEMM_PRELUDE(A, B, K)

    // ---- epilogue: stage B1 slice (8 experts x 128 h x 16 fp16 = 32KB),
    //      t1 for 256 slots (16KB), sel (1KB), b1 (0.5KB) ----
    __syncthreads();
    __half* B1s  = smh;                                   // 32768 B
    float*  t1s  = (float*)(smh + 16384);                 // 16384 B
    int*    sels = (int*)(smh + 16384 + 8192);            // 1024 B
    float*  b1s  = (float*)(smh + 16384 + 8192 + 512);    // 512 B

    for (int idx = tid; idx < E_NUM * 128; idx += 256) {
        int e = idx >> 7, hl = idx & 127;
        const float4* src = (const float4*)(B1mat + ((size_t)e * H_DIM + bn + hl) * R_DIM);
        float4 v0 = src[0], v1 = src[1], v2 = src[2], v3 = src[3];
        __half2 hv[8];
        hv[0] = __floats2half2_rn(v0.x, v0.y); hv[1] = __floats2half2_rn(v0.z, v0.w);
        hv[2] = __floats2half2_rn(v1.x, v1.y); hv[3] = __floats2half2_rn(v1.z, v1.w);
        hv[4] = __floats2half2_rn(v2.x, v2.y); hv[5] = __floats2half2_rn(v2.z, v2.w);
        hv[6] = __floats2half2_rn(v3.x, v3.y); hv[7] = __floats2half2_rn(v3.z, v3.w);
        uint4* dst = (uint4*)(B1s + idx * 16);
        dst[0] = ((uint4*)hv)[0];
        dst[1] = ((uint4*)hv)[1];
    }
    for (int idx = tid; idx < 1024; idx += 256)
        ((float4*)t1s)[idx] = *(const float4*)(g_t1 + (size_t)(2 * bm) * R_DIM + idx * 4);
    if (tid < 128) {
        b1s[tid] = b1[bn + tid];
    }
    for (int idx = tid; idx < 256; idx += 256)
        sels[idx] = g_sel[2 * bm + idx];
    __syncthreads();

    #pragma unroll
    for (int mt = 0; mt < 2; mt++) {
        #pragma unroll
        for (int rh = 0; rh < 2; rh++) {
            int lt = wm + mt * 16 + g + rh * 8;          // local token 0..127
            int lp0 = 2 * lt, lp1 = 2 * lt + 1;
            int e0 = sels[lp0], e1 = sels[lp1];
            const float* ta = t1s + lp0 * R_DIM;
            const float* tb = t1s + lp1 * R_DIM;
            __half* o0 = g_acth + (size_t)(2 * bm + lp0) * H_DIM + bn;
            __half* o1 = g_acth + (size_t)(2 * bm + lp1) * H_DIM + bn;
            #pragma unroll
            for (int nt = 0; nt < 8; nt++) {
                int c0 = wn + nt * 8 + 2 * tg;
                float a0[2], a1[2];
                #pragma unroll
                for (int j = 0; j < 2; j++) {
                    int hl = c0 + j;
                    float base = acc[mt][nt][rh * 2 + j] + b1s[hl];
                    float l0 = dot16h(ta, B1s + ((size_t)e0 * 128 + hl) * 16);
                    float l1 = dot16h(tb, B1s + ((size_t)e1 * 128 + hl) * 16);
                    a0[j] = fast_silu(base + LSCALE * l0);
                    a1[j] = fast_silu(base + LSCALE * l1);
                }
                *(__half2*)(o0 + c0) = __floats2half2_rn(a0[0], a0[1]);
                *(__half2*)(o1 + c0) = __floats2half2_rn(a1[0], a1[1]);
            }
        }
    }
}

// ---------------- GEMM2 + bias + LoRA-up + weighted combine (smem-staged epilogue) ----------------
__global__ __launch_bounds__(256)
void gemm2_combine_kernel(const __half* __restrict__ A, const __half* __restrict__ B,
                          const float* __restrict__ b2, const float* __restrict__ B2mat,
                          float* __restrict__ out, int M, int N, int K) {
    extern __shared__ __half smh[];
    GEMM_PRELUDE(A, B, K)

    // ---- epilogue: stage operands in smem (reuse pipeline buffers) ----
    __syncthreads();
    __half* B2s = smh;                               // [E_NUM][128][16] fp16 = 32KB
    float*  t2s = (float*)(smh + 16384);             // [128][16] = 8KB
    float*  wts = (float*)(smh + 16384 + 4096);      // [128]
    int*    sels = (int*)(smh + 16384 + 4096 + 256); // [128]
    float*  b2s = (float*)(smh + 16384 + 4096 + 512);// [128]

    for (int idx = tid; idx < E_NUM * 128; idx += 256) {
        int e = idx >> 7, dl = idx & 127;
        const float4* src = (const float4*)(B2mat + ((size_t)e * D_DIM + bn + dl) * R_DIM);
        float4 v0 = src[0], v1 = src[1], v2 = src[2], v3 = src[3];
        __half2 hv[8];
        hv[0] = __floats2half2_rn(v0.x, v0.y); hv[1] = __floats2half2_rn(v0.z, v0.w);
        hv[2] = __floats2half2_rn(v1.x, v1.y); hv[3] = __floats2half2_rn(v1.z, v1.w);
        hv[4] = __floats2half2_rn(v2.x, v2.y); hv[5] = __floats2half2_rn(v2.z, v2.w);
        hv[6] = __floats2half2_rn(v3.x, v3.y); hv[7] = __floats2half2_rn(v3.z, v3.w);
        uint4* dst = (uint4*)(B2s + idx * 16);
        dst[0] = ((uint4*)hv)[0];
        dst[1] = ((uint4*)hv)[1];
    }
    for (int idx = tid; idx < 512; idx += 256)
        ((float4*)t2s)[idx] = *(const float4*)(g_t2 + (size_t)bm * R_DIM + idx * 4);
    if (tid < 128) {
        wts[tid] = g_wt[bm + tid];
        sels[tid] = g_sel[bm + tid];
        b2s[tid] = b2[bn + tid];
    }
    __syncthreads();

    #pragma unroll
    for (int mt = 0; mt < 2; mt++) {
        #pragma unroll
        for (int rh = 0; rh < 2; rh++) {
            int lp = wm + mt * 16 + g + rh * 8;   // local slot; parity = g&1
            int e = sels[lp];
            float w = wts[lp];
            const float* tv = t2s + lp * R_DIM;
            float* orow = out + (size_t)((bm + lp) >> 1) * D_DIM;
            #pragma unroll
            for (int nt = 0; nt < 8; nt++) {
                int c0 = wn + nt * 8 + 2 * tg;
                float wv[2];
                #pragma unroll
                for (int j = 0; j < 2; j++) {
                    int dl = c0 + j;
                    float dot = dot16h(tv, B2s + ((size_t)e * 128 + dl) * 16);
                    wv[j] = w * (acc[mt][nt][rh * 2 + j] + b2s[dl] + LSCALE * dot);
                }
                float pv0 = __shfl_xor_sync(0xffffffffu, wv[0], 4);
                float pv1 = __shfl_xor_sync(0xffffffffu, wv[1], 4);
                if (!(g & 1))
                    *(float2*)(orow + bn + c0) = make_float2(wv[0] + pv0, wv[1] + pv1);
            }
        }
    }
}

// ---------------- grouped rank-16 down-projection (fp16 input rows) ----------------
#define GL_G 32
#define GL_KC 128
__global__ __launch_bounds__(256)
void lora_in_grouped_h(const __half* __restrict__ X, const float* __restrict__ Amat,
                       float* __restrict__ Tout, int K, int tok_row) {
    int e = blockIdx.y;
    int n_e = g_cnt[e];
    int base = blockIdx.x * GL_G;
    if (base >= n_e) return;
    __shared__ float As[R_DIM][GL_KC];
    __shared__ int sl[GL_G];
    int tid = threadIdx.x, lane = tid & 31, w = tid >> 5;
    if (tid < GL_G) {
        int j = base + tid;
        sl[tid] = (j < n_e) ? g_list[g_off[e] + j] : -1;
    }
    __syncthreads();
    int p[4];
    const __half* xr[4];
    #pragma unroll
    for (int s = 0; s < 4; s++) {
        p[s] = sl[w * 4 + s];
        int row = (p[s] < 0) ? 0 : (tok_row ? (p[s] >> 1) : p[s]);
        xr[s] = X + (size_t)row * K;
    }
    float acc[4][R_DIM];
    #pragma unroll
    for (int s = 0; s < 4; s++)
        #pragma unroll
        for (int r = 0; r < R_DIM; r++) acc[s][r] = 0.f;

    const float* Ae = Amat + (size_t)e * R_DIM * K;
    for (int k0 = 0; k0 < K; k0 += GL_KC) {
        __syncthreads();
        #pragma unroll
        for (int l = 0; l < 2; l++) {
            int i = tid * 2 + l;
            int r = i >> 5, kq = i & 31;
            *(float4*)&As[r][kq * 4] = *(const float4*)(Ae + (size_t)r * K + k0 + kq * 4);
        }
        __syncthreads();
        float4 xv[4];
        #pragma unroll
        for (int s = 0; s < 4; s++) {
            __half2 h01 = *(const __half2*)(xr[s] + k0 + lane * 4);
            __half2 h23 = *(const __half2*)(xr[s] + k0 + lane * 4 + 2);
            float2 f01 = __half22float2(h01);
            float2 f23 = __half22float2(h23);
            xv[s] = make_float4(f01.x, f01.y, f23.x, f23.y);
        }
        #pragma unroll
        for (int r = 0; r < R_DIM; r++) {
            float4 a4 = *(const float4*)&As[r][lane * 4];
            #pragma unroll
            for (int s = 0; s < 4; s++)
                acc[s][r] += xv[s].x * a4.x + xv[s].y * a4.y + xv[s].z * a4.z + xv[s].w * a4.w;
        }
    }
    #pragma unroll
    for (int s = 0; s < 4; s++) {
        #pragma unroll
        for (int r = 0; r < R_DIM; r++) {
            float v = acc[s][r];
            v += __shfl_xor_sync(0xffffffffu, v, 16);
            v += __shfl_xor_sync(0xffffffffu, v, 8);
            v += __shfl_xor_sync(0xffffffffu, v, 4);
            v += __shfl_xor_sync(0xffffffffu, v, 2);
            v += __shfl_xor_sync(0xffffffffu, v, 1);
            if (lane == 0 && p[s] >= 0) Tout[p[s] * R_DIM + r] = v;
        }
    }
}

// ---------------- launch ----------------
extern "C" void kernel_launch(void* const* d_in, const int* in_sizes, int n_in,
                              void* d_out, int out_size) {
    const float* x    = (const float*)d_in[0];
    const float* gate = (const float*)d_in[1];
    const float* W1   = (const float*)d_in[2];
    const float* b1   = (const float*)d_in[3];
    const float* W2   = (const float*)d_in[4];
    const float* b2   = (const float*)d_in[5];
    const float* A1   = (const float*)d_in[6];
    const float* B1   = (const float*)d_in[7];
    const float* A2   = (const float*)d_in[8];
    const float* B2   = (const float*)d_in[9];
    float* out = (float*)d_out;

    float *p_t1, *p_t2;
    __half *p_xh, *p_w1h, *p_w2h, *p_acth;
    cudaGetSymbolAddress((void**)&p_t1,   g_t1);
    cudaGetSymbolAddress((void**)&p_t2,   g_t2);
    cudaGetSymbolAddress((void**)&p_xh,   g_xh);
    cudaGetSymbolAddress((void**)&p_w1h,  g_w1h);
    cudaGetSymbolAddress((void**)&p_w2h,  g_w2h);
    cudaGetSymbolAddress((void**)&p_acth, g_acth);

    cudaFuncSetAttribute(gemm1_act_kernel,
                         cudaFuncAttributeMaxDynamicSharedMemorySize, GSMEM);
    cudaFuncSetAttribute(gemm2_combine_kernel,
                         cudaFuncAttributeMaxDynamicSharedMemorySize, GSMEM);

    // 0. fp16 copies of GEMM inputs (first also zeroes expert counts)
    cvt_f32_f16<<<(N_TOK * D_DIM) / 2048, 256>>>(x, p_xh, N_TOK * D_DIM);
    cvt_f32_f16<<<(H_DIM * D_DIM) / 2048, 256>>>(W1, p_w1h, H_DIM * D_DIM);
    cvt_f32_f16<<<(D_DIM * H_DIM) / 2048, 256>>>(W2, p_w2h, D_DIM * H_DIM);

    // 1. router (fused expert count)
    router_kernel<<<N_TOK, 256>>>(x, gate);

    // 2. dispatch
    dispatch_prefix<<<1, 32>>>();
    dispatch_scatter<<<NSLOT / 256, 256>>>();

    // 3. t1 = x @ A1[e]^T (needed by GEMM1 epilogue)
    lora_in_grouped_h<<<dim3(NSLOT / GL_G, E_NUM), 256>>>(p_xh, A1, p_t1, D_DIM, 1);

    // 4. acth = silu(X@W1^T + b1 + LSCALE * t1 @ B1[e]^T)  (fused, smem-staged)
    {
        dim3 grid(H_DIM / 128, N_TOK / 128);
        gemm1_act_kernel<<<grid, 256, GSMEM>>>(p_xh, p_w1h, b1, B1, N_TOK, H_DIM, D_DIM);
    }

    // 5. t2 = a @ A2[e]^T
    lora_in_grouped_h<<<dim3(NSLOT / GL_G, E_NUM), 256>>>(p_acth, A2, p_t2, H_DIM, 0);

    // 6. out = sum_k w_k * (a@W2^T + b2 + LSCALE * t2 @ B2[e]^T)  (fused, smem-staged)
    {
        dim3 grid(D_DIM / 128, NSLOT / 128);
        gemm2_combine_kernel<<<grid, 256, GSMEM>>>(p_acth, p_w2h, b2, B2, out, NSLOT, D_DIM, H_DIM);
    }
}

// round 16
// speedup vs baseline: 1.4627x; 1.0239x over previous
#include <cuda_runtime.h>
#include <cuda_fp16.h>
#include <math.h>
#include <stdint.h>

#define N_TOK 2048
#define D_DIM 1024
#define H_DIM 4096
#define E_NUM 8
#define R_DIM 16
#define LSCALE 2.0f
#define NSLOT (2*N_TOK)

// ---------------- scratch ----------------
__device__ __half g_acth[NSLOT * H_DIM];
__device__ float  g_t1[NSLOT * R_DIM];
__device__ float  g_t2[NSLOT * R_DIM];
__device__ int    g_sel[NSLOT];
__device__ float  g_wt[NSLOT];
__device__ int g_cnt[E_NUM];
__device__ int g_off[E_NUM];
__device__ int g_pos[E_NUM];
__device__ int g_list[NSLOT];
__device__ __half g_xh[N_TOK * D_DIM];
__device__ __half g_w1h[H_DIM * D_DIM];
__device__ __half g_w2h[D_DIM * H_DIM];

// ---------------- fused f32 -> f16 conversion of x, W1, W2 (one launch) ----------------
// chunk = 8 elems. Segments: x, W1, W2.
#define XCH (N_TOK * D_DIM / 8)
#define W1CH (H_DIM * D_DIM / 8)
__global__ void cvt_all(const float* __restrict__ x, const float* __restrict__ W1,
                        const float* __restrict__ W2) {
    if (blockIdx.x == 0 && threadIdx.x < E_NUM) g_cnt[threadIdx.x] = 0;
    int c = blockIdx.x * 256 + threadIdx.x;
    const float* in;
    __half* out;
    int lo;
    if (c < XCH) {
        in = x; lo = c;
        out = g_xh;
    } else if (c < XCH + W1CH) {
        in = W1; lo = c - XCH;
        out = g_w1h;
    } else {
        in = W2; lo = c - XCH - W1CH;
        out = g_w2h;
    }
    int i = lo * 8;
    float4 v0 = *(const float4*)(in + i);
    float4 v1 = *(const float4*)(in + i + 4);
    __half2 h[4];
    h[0] = __floats2half2_rn(v0.x, v0.y);
    h[1] = __floats2half2_rn(v0.z, v0.w);
    h[2] = __floats2half2_rn(v1.x, v1.y);
    h[3] = __floats2half2_rn(v1.z, v1.w);
    *(uint4*)(out + i) = *(uint4*)h;
}

// ---------------- router: 4 tokens/block, gate staged in smem ----------------
__global__ __launch_bounds__(256)
void router_kernel(const float* __restrict__ x, const float* __restrict__ gate) {
    __shared__ float gs[E_NUM * D_DIM];   // 32 KB
    __shared__ float lg[4][E_NUM];
    int tid = threadIdx.x, warp = tid >> 5, lane = tid & 31;
    for (int i = tid; i < E_NUM * D_DIM / 4; i += 256)
        ((float4*)gs)[i] = ((const float4*)gate)[i];
    __syncthreads();
    #pragma unroll
    for (int t = 0; t < 4; t++) {
        int tok = blockIdx.x * 4 + t;
        const float4* xr = (const float4*)(x + (size_t)tok * D_DIM);
        const float4* gr = (const float4*)(gs + warp * D_DIM);
        float s = 0.f;
        for (int i = lane; i < D_DIM / 4; i += 32) {
            float4 a = xr[i], b = gr[i];
            s += a.x * b.x + a.y * b.y + a.z * b.z + a.w * b.w;
        }
        #pragma unroll
        for (int o = 16; o; o >>= 1) s += __shfl_xor_sync(0xffffffffu, s, o);
        if (lane == 0) lg[t][warp] = s;
    }
    __syncthreads();
    if (tid < 4) {
        int tok = blockIdx.x * 4 + tid;
        float best = -1e30f; int i0 = 0;
        #pragma unroll
        for (int e = 0; e < E_NUM; e++) if (lg[tid][e] > best) { best = lg[tid][e]; i0 = e; }
        float best2 = -1e30f; int i1 = 0;
        #pragma unroll
        for (int e = 0; e < E_NUM; e++) if (e != i0 && lg[tid][e] > best2) { best2 = lg[tid][e]; i1 = e; }
        float p1 = expf(best2 - best);
        float inv = 1.f / (1.f + p1);
        g_sel[tok * 2 + 0] = i0; g_sel[tok * 2 + 1] = i1;
        g_wt[tok * 2 + 0] = inv; g_wt[tok * 2 + 1] = p1 * inv;
        atomicAdd(&g_cnt[i0], 1);
        atomicAdd(&g_cnt[i1], 1);
    }
}

// ---------------- dispatch ----------------
__global__ void dispatch_prefix() {
    if (threadIdx.x == 0) {
        int o = 0;
        for (int e = 0; e < E_NUM; e++) { g_off[e] = o; g_pos[e] = o; o += g_cnt[e]; }
    }
}
__global__ void dispatch_scatter() {
    int i = blockIdx.x * 256 + threadIdx.x;
    if (i < NSLOT) {
        int e = g_sel[i];
        int pos = atomicAdd(&g_pos[e], 1);
        g_list[pos] = i;
    }
}

// ---------------- GEMM machinery ----------------
__device__ __forceinline__ void mma_f16(float* c, const unsigned* a, const unsigned* b) {
    asm volatile(
        "mma.sync.aligned.m16n8k16.row.col.f32.f16.f16.f32 "
        "{%0,%1,%2,%3}, {%4,%5,%6,%7}, {%8,%9}, {%0,%1,%2,%3};"
        : "+f"(c[0]), "+f"(c[1]), "+f"(c[2]), "+f"(c[3])
        : "r"(a[0]), "r"(a[1]), "r"(a[2]), "r"(a[3]), "r"(b[0]), "r"(b[1]));
}
__device__ __forceinline__ void ldsm_x4(unsigned* r, uint32_t addr) {
    asm volatile("ldmatrix.sync.aligned.m8n8.x4.shared.b16 {%0,%1,%2,%3}, [%4];"
        : "=r"(r[0]), "=r"(r[1]), "=r"(r[2]), "=r"(r[3]) : "r"(addr));
}
__device__ __forceinline__ uint32_t smem_u32(const void* p) {
    uint32_t a;
    asm("{ .reg .u64 t; cvta.to.shared.u64 t, %1; cvt.u32.u64 %0, t; }" : "=r"(a) : "l"(p));
    return a;
}
__device__ __forceinline__ void cp_async16(uint32_t dst, const void* src) {
    asm volatile("cp.async.cg.shared.global [%0], [%1], 16;" :: "r"(dst), "l"(src));
}
#define CP_COMMIT() asm volatile("cp.async.commit_group;" ::: "memory")
#define CP_WAIT(n)  asm volatile("cp.async.wait_group %0;" :: "n"(n) : "memory")

#define GSTRH 40
#define GHTILE (128 * GSTRH)
#define GSTAGEB (2 * GHTILE * 2)
#define GSMEM (3 * GSTAGEB)

// common mainloop prelude macro (R11-identical)
#define GEMM_PRELUDE(A, B, K)                                                            \
    uint32_t sb = smem_u32(smh);                                                         \
    int bm = blockIdx.y * 128, bn = blockIdx.x * 128;                                    \
    int tid = threadIdx.x;                                                               \
    int lane = tid & 31, wid = tid >> 5;                                                 \
    int wm = (wid >> 1) * 32, wn = (wid & 1) * 64;                                       \
    int g = lane >> 2, tg = lane & 3;                                                    \
    int row0 = (tid * 2) >> 2,     q0 = (tid * 2) & 3;                                   \
    int row1 = (tid * 2 + 1) >> 2, q1 = (tid * 2 + 1) & 3;                               \
    const char* Ap0 = (const char*)(A + (size_t)(bm + row0) * K + q0 * 8);               \
    const char* Ap1 = (const char*)(A + (size_t)(bm + row1) * K + q1 * 8);               \
    const char* Bp0 = (const char*)(B + (size_t)(bn + row0) * K + q0 * 8);               \
    const char* Bp1 = (const char*)(B + (size_t)(bn + row1) * K + q1 * 8);               \
    uint32_t oA0 = (uint32_t)(row0 * GSTRH + q0 * 8) * 2;                                \
    uint32_t oA1 = (uint32_t)(row1 * GSTRH + q1 * 8) * 2;                                \
    uint32_t oB0 = (uint32_t)GHTILE * 2 + oA0;                                           \
    uint32_t oB1 = (uint32_t)GHTILE * 2 + oA1;                                           \
    uint32_t laA[2];                                                                     \
    _Pragma("unroll")                                                                    \
    for (int mt = 0; mt < 2; mt++)                                                       \
        laA[mt] = (uint32_t)((wm + mt * 16 + (lane & 15)) * GSTRH +                      \
                             ((lane & 16) ? 8 : 0)) * 2;                                 \
    uint32_t laB[4];                                                                     \
    _Pragma("unroll")                                                                    \
    for (int p = 0; p < 4; p++)                                                          \
        laB[p] = (uint32_t)GHTILE * 2 +                                                  \
                 (uint32_t)((wn + 16 * p + (lane & 7) + ((lane & 16) ? 8 : 0)) * GSTRH + \
                            ((lane & 8) ? 8 : 0)) * 2;                                   \
    float acc[2][8][4];                                                                  \
    _Pragma("unroll")                                                                    \
    for (int mt = 0; mt < 2; mt++)                                                       \
        _Pragma("unroll")                                                                \
        for (int nt = 0; nt < 8; nt++)                                                   \
            _Pragma("unroll")                                                            \
            for (int i = 0; i < 4; i++) acc[mt][nt][i] = 0.f;                            \
    int ntk = K >> 5;                                                                    \
    _Pragma("unroll")                                                                    \
    for (int s = 0; s < 2; s++) {                                                        \
        uint32_t st = sb + s * GSTAGEB;                                                  \
        size_t ko = (size_t)s * 64;                                                      \
        cp_async16(st + oA0, Ap0 + ko); cp_async16(st + oA1, Ap1 + ko);                  \
        cp_async16(st + oB0, Bp0 + ko); cp_async16(st + oB1, Bp1 + ko);                  \
        CP_COMMIT();                                                                     \
    }                                                                                    \
    for (int kt = 0; kt < ntk; kt++) {                                                   \
        int b = kt % 3;                                                                  \
        if (kt + 1 < ntk) { CP_WAIT(1); } else { CP_WAIT(0); }                           \
        __syncthreads();                                                                 \
        if (kt + 2 < ntk) {                                                              \
            int s = (kt + 2) % 3;                                                        \
            uint32_t st = sb + s * GSTAGEB;                                              \
            size_t ko = (size_t)(kt + 2) * 64;                                           \
            cp_async16(st + oA0, Ap0 + ko); cp_async16(st + oA1, Ap1 + ko);              \
            cp_async16(st + oB0, Bp0 + ko); cp_async16(st + oB1, Bp1 + ko);              \
            CP_COMMIT();                                                                 \
        }                                                                                \
        uint32_t stg = sb + b * GSTAGEB;                                                 \
        _Pragma("unroll")                                                                \
        for (int kg = 0; kg < 2; kg++) {                                                 \
            uint32_t kofs = kg * 32;                                                     \
            unsigned av[2][4], bv[4][4];                                                 \
            _Pragma("unroll")                                                            \
            for (int mt = 0; mt < 2; mt++)                                               \
                ldsm_x4(av[mt], stg + laA[mt] + kofs);                                   \
            _Pragma("unroll")                                                            \
            for (int p = 0; p < 4; p++)                                                  \
                ldsm_x4(bv[p], stg + laB[p] + kofs);                                     \
            _Pragma("unroll")                                                            \
            for (int mt = 0; mt < 2; mt++)                                               \
                _Pragma("unroll")                                                        \
                for (int nt = 0; nt < 8; nt++)                                           \
                    mma_f16(acc[mt][nt], av[mt], &bv[nt >> 1][(nt & 1) * 2]);            \
        }                                                                                \
    }

// smem-resident rank-16 dot: t (fp32[16]) . brow (fp16[16])
__device__ __forceinline__ float dot16h(const float* tv, const __half* brow) {
    const uint4* bp = (const uint4*)brow;
    uint4 u0 = bp[0], u1 = bp[1];
    const __half2* hp = (const __half2*)&u0;
    const __half2* hq = (const __half2*)&u1;
    float dot = 0.f;
    #pragma unroll
    for (int q = 0; q < 4; q++) {
        float2 f = __half22float2(hp[q]);
        dot += tv[q * 2] * f.x + tv[q * 2 + 1] * f.y;
    }
    #pragma unroll
    for (int q = 0; q < 4; q++) {
        float2 f = __half22float2(hq[q]);
        dot += tv[8 + q * 2] * f.x + tv[8 + q * 2 + 1] * f.y;
    }
    return dot;
}
__device__ __forceinline__ float fast_silu(float v) {
    return __fdividef(v, 1.f + __expf(-v));
}

// ---------------- GEMM1 + bias + LoRA-up + silu -> acth (smem-staged epilogue) ----------------
__global__ __launch_bounds__(256)
void gemm1_act_kernel(const __half* __restrict__ A, const __half* __restrict__ B,
                      const float* __restrict__ b1, const float* __restrict__ B1mat,
                      int M, int N, int K) {
    extern __shared__ __half smh[];
    GEMM_PRELUDE(A, B, K)

    __syncthreads();
    __half* B1s  = smh;                                   // 32768 B
    float*  t1s  = (float*)(smh + 16384);                 // 16384 B
    int*    sels = (int*)(smh + 16384 + 8192);            // 1024 B
    float*  b1s  = (float*)(smh + 16384 + 8192 + 512);    // 512 B

    for (int idx = tid; idx < E_NUM * 128; idx += 256) {
        int e = idx >> 7, hl = idx & 127;
        const float4* src = (const float4*)(B1mat + ((size_t)e * H_DIM + bn + hl) * R_DIM);
        float4 v0 = src[0], v1 = src[1], v2 = src[2], v3 = src[3];
        __half2 hv[8];
        hv[0] = __floats2half2_rn(v0.x, v0.y); hv[1] = __floats2half2_rn(v0.z, v0.w);
        hv[2] = __floats2half2_rn(v1.x, v1.y); hv[3] = __floats2half2_rn(v1.z, v1.w);
        hv[4] = __floats2half2_rn(v2.x, v2.y); hv[5] = __floats2half2_rn(v2.z, v2.w);
        hv[6] = __floats2half2_rn(v3.x, v3.y); hv[7] = __floats2half2_rn(v3.z, v3.w);
        uint4* dst = (uint4*)(B1s + idx * 16);
        dst[0] = ((uint4*)hv)[0];
        dst[1] = ((uint4*)hv)[1];
    }
    for (int idx = tid; idx < 1024; idx += 256)
        ((float4*)t1s)[idx] = *(const float4*)(g_t1 + (size_t)(2 * bm) * R_DIM + idx * 4);
    if (tid < 128) {
        b1s[tid] = b1[bn + tid];
    }
    for (int idx = tid; idx < 256; idx += 256)
        sels[idx] = g_sel[2 * bm + idx];
    __syncthreads();

    #pragma unroll
    for (int mt = 0; mt < 2; mt++) {
        #pragma unroll
        for (int rh = 0; rh < 2; rh++) {
            int lt = wm + mt * 16 + g + rh * 8;
            int lp0 = 2 * lt, lp1 = 2 * lt + 1;
            int e0 = sels[lp0], e1 = sels[lp1];
            const float* ta = t1s + lp0 * R_DIM;
            const float* tb = t1s + lp1 * R_DIM;
            __half* o0 = g_acth + (size_t)(2 * bm + lp0) * H_DIM + bn;
            __half* o1 = g_acth + (size_t)(2 * bm + lp1) * H_DIM + bn;
            #pragma unroll
            for (int nt = 0; nt < 8; nt++) {
                int c0 = wn + nt * 8 + 2 * tg;
                float a0[2], a1[2];
                #pragma unroll
                for (int j = 0; j < 2; j++) {
                    int hl = c0 + j;
                    float base = acc[mt][nt][rh * 2 + j] + b1s[hl];
                    float l0 = dot16h(ta, B1s + ((size_t)e0 * 128 + hl) * 16);
                    float l1 = dot16h(tb, B1s + ((size_t)e1 * 128 + hl) * 16);
                    a0[j] = fast_silu(base + LSCALE * l0);
                    a1[j] = fast_silu(base + LSCALE * l1);
                }
                *(__half2*)(o0 + c0) = __floats2half2_rn(a0[0], a0[1]);
                *(__half2*)(o1 + c0) = __floats2half2_rn(a1[0], a1[1]);
            }
        }
    }
}

// ---------------- GEMM2 + bias + LoRA-up + weighted combine (smem-staged epilogue) ----------------
__global__ __launch_bounds__(256)
void gemm2_combine_kernel(const __half* __restrict__ A, const __half* __restrict__ B,
                          const float* __restrict__ b2, const float* __restrict__ B2mat,
                          float* __restrict__ out, int M, int N, int K) {
    extern __shared__ __half smh[];
    GEMM_PRELUDE(A, B, K)

    __syncthreads();
    __half* B2s = smh;                               // 32KB
    float*  t2s = (float*)(smh + 16384);             // 8KB
    float*  wts = (float*)(smh + 16384 + 4096);      // [128]
    int*    sels = (int*)(smh + 16384 + 4096 + 256); // [128]
    float*  b2s = (float*)(smh + 16384 + 4096 + 512);// [128]

    for (int idx = tid; idx < E_NUM * 128; idx += 256) {
        int e = idx >> 7, dl = idx & 127;
        const float4* src = (const float4*)(B2mat + ((size_t)e * D_DIM + bn + dl) * R_DIM);
        float4 v0 = src[0], v1 = src[1], v2 = src[2], v3 = src[3];
        __half2 hv[8];
        hv[0] = __floats2half2_rn(v0.x, v0.y); hv[1] = __floats2half2_rn(v0.z, v0.w);
        hv[2] = __floats2half2_rn(v1.x, v1.y); hv[3] = __floats2half2_rn(v1.z, v1.w);
        hv[4] = __floats2half2_rn(v2.x, v2.y); hv[5] = __floats2half2_rn(v2.z, v2.w);
        hv[6] = __floats2half2_rn(v3.x, v3.y); hv[7] = __floats2half2_rn(v3.z, v3.w);
        uint4* dst = (uint4*)(B2s + idx * 16);
        dst[0] = ((uint4*)hv)[0];
        dst[1] = ((uint4*)hv)[1];
    }
    for (int idx = tid; idx < 512; idx += 256)
        ((float4*)t2s)[idx] = *(const float4*)(g_t2 + (size_t)bm * R_DIM + idx * 4);
    if (tid < 128) {
        wts[tid] = g_wt[bm + tid];
        sels[tid] = g_sel[bm + tid];
        b2s[tid] = b2[bn + tid];
    }
    __syncthreads();

    #pragma unroll
    for (int mt = 0; mt < 2; mt++) {
        #pragma unroll
        for (int rh = 0; rh < 2; rh++) {
            int lp = wm + mt * 16 + g + rh * 8;
            int e = sels[lp];
            float w = wts[lp];
            const float* tv = t2s + lp * R_DIM;
            float* orow = out + (size_t)((bm + lp) >> 1) * D_DIM;
            #pragma unroll
            for (int nt = 0; nt < 8; nt++) {
                int c0 = wn + nt * 8 + 2 * tg;
                float wv[2];
                #pragma unroll
                for (int j = 0; j < 2; j++) {
                    int dl = c0 + j;
                    float dot = dot16h(tv, B2s + ((size_t)e * 128 + dl) * 16);
                    wv[j] = w * (acc[mt][nt][rh * 2 + j] + b2s[dl] + LSCALE * dot);
                }
                float pv0 = __shfl_xor_sync(0xffffffffu, wv[0], 4);
                float pv1 = __shfl_xor_sync(0xffffffffu, wv[1], 4);
                if (!(g & 1))
                    *(float2*)(orow + bn + c0) = make_float2(wv[0] + pv0, wv[1] + pv1);
            }
        }
    }
}

// ---------------- grouped rank-16 down-projection (fp16 input rows) ----------------
#define GL_G 32
#define GL_KC 128
__global__ __launch_bounds__(256)
void lora_in_grouped_h(const __half* __restrict__ X, const float* __restrict__ Amat,
                       float* __restrict__ Tout, int K, int tok_row) {
    int e = blockIdx.y;
    int n_e = g_cnt[e];
    int base = blockIdx.x * GL_G;
    if (base >= n_e) return;
    __shared__ float As[R_DIM][GL_KC];
    __shared__ int sl[GL_G];
    int tid = threadIdx.x, lane = tid & 31, w = tid >> 5;
    if (tid < GL_G) {
        int j = base + tid;
        sl[tid] = (j < n_e) ? g_list[g_off[e] + j] : -1;
    }
    __syncthreads();
    int p[4];
    const __half* xr[4];
    #pragma unroll
    for (int s = 0; s < 4; s++) {
        p[s] = sl[w * 4 + s];
        int row = (p[s] < 0) ? 0 : (tok_row ? (p[s] >> 1) : p[s]);
        xr[s] = X + (size_t)row * K;
    }
    float acc[4][R_DIM];
    #pragma unroll
    for (int s = 0; s < 4; s++)
        #pragma unroll
        for (int r = 0; r < R_DIM; r++) acc[s][r] = 0.f;

    const float* Ae = Amat + (size_t)e * R_DIM * K;
    for (int k0 = 0; k0 < K; k0 += GL_KC) {
        __syncthreads();
        #pragma unroll
        for (int l = 0; l < 2; l++) {
            int i = tid * 2 + l;
            int r = i >> 5, kq = i & 31;
            *(float4*)&As[r][kq * 4] = *(const float4*)(Ae + (size_t)r * K + k0 + kq * 4);
        }
        __syncthreads();
        float4 xv[4];
        #pragma unroll
        for (int s = 0; s < 4; s++) {
            __half2 h01 = *(const __half2*)(xr[s] + k0 + lane * 4);
            __half2 h23 = *(const __half2*)(xr[s] + k0 + lane * 4 + 2);
            float2 f01 = __half22float2(h01);
            float2 f23 = __half22float2(h23);
            xv[s] = make_float4(f01.x, f01.y, f23.x, f23.y);
        }
        #pragma unroll
        for (int r = 0; r < R_DIM; r++) {
            float4 a4 = *(const float4*)&As[r][lane * 4];
            #pragma unroll
            for (int s = 0; s < 4; s++)
                acc[s][r] += xv[s].x * a4.x + xv[s].y * a4.y + xv[s].z * a4.z + xv[s].w * a4.w;
        }
    }
    #pragma unroll
    for (int s = 0; s < 4; s++) {
        #pragma unroll
        for (int r = 0; r < R_DIM; r++) {
            float v = acc[s][r];
            v += __shfl_xor_sync(0xffffffffu, v, 16);
            v += __shfl_xor_sync(0xffffffffu, v, 8);
            v += __shfl_xor_sync(0xffffffffu, v, 4);
            v += __shfl_xor_sync(0xffffffffu, v, 2);
            v += __shfl_xor_sync(0xffffffffu, v, 1);
            if (lane == 0 && p[s] >= 0) Tout[p[s] * R_DIM + r] = v;
        }
    }
}

// ---------------- launch ----------------
extern "C" void kernel_launch(void* const* d_in, const int* in_sizes, int n_in,
                              void* d_out, int out_size) {
    const float* x    = (const float*)d_in[0];
    const float* gate = (const float*)d_in[1];
    const float* W1   = (const float*)d_in[2];
    const float* b1   = (const float*)d_in[3];
    const float* W2   = (const float*)d_in[4];
    const float* b2   = (const float*)d_in[5];
    const float* A1   = (const float*)d_in[6];
    const float* B1   = (const float*)d_in[7];
    const float* A2   = (const float*)d_in[8];
    const float* B2   = (const float*)d_in[9];
    float* out = (float*)d_out;

    float *p_t1, *p_t2;
    __half *p_xh, *p_w1h, *p_w2h, *p_acth;
    cudaGetSymbolAddress((void**)&p_t1,   g_t1);
    cudaGetSymbolAddress((void**)&p_t2,   g_t2);
    cudaGetSymbolAddress((void**)&p_xh,   g_xh);
    cudaGetSymbolAddress((void**)&p_w1h,  g_w1h);
    cudaGetSymbolAddress((void**)&p_w2h,  g_w2h);
    cudaGetSymbolAddress((void**)&p_acth, g_acth);

    cudaFuncSetAttribute(gemm1_act_kernel,
                         cudaFuncAttributeMaxDynamicSharedMemorySize, GSMEM);
    cudaFuncSetAttribute(gemm2_combine_kernel,
                         cudaFuncAttributeMaxDynamicSharedMemorySize, GSMEM);

    // 0. fused fp16 conversion of x, W1, W2 (also zeroes expert counts)
    {
        int chunks = XCH + 2 * W1CH;
        cvt_all<<<chunks / 256, 256>>>(x, W1, W2);
    }

    // 1. router (gate staged in smem, 4 tokens/block, fused expert count)
    router_kernel<<<N_TOK / 4, 256>>>(x, gate);

    // 2. dispatch
    dispatch_prefix<<<1, 32>>>();
    dispatch_scatter<<<NSLOT / 256, 256>>>();

    // 3. t1 = x @ A1[e]^T
    lora_in_grouped_h<<<dim3(NSLOT / GL_G, E_NUM), 256>>>(p_xh, A1, p_t1, D_DIM, 1);

    // 4. acth = silu(X@W1^T + b1 + LSCALE * t1 @ B1[e]^T)  (fused, smem-staged)
    {
        dim3 grid(H_DIM / 128, N_TOK / 128);
        gemm1_act_kernel<<<grid, 256, GSMEM>>>(p_xh, p_w1h, b1, B1, N_TOK, H_DIM, D_DIM);
    }

    // 5. t2 = a @ A2[e]^T
    lora_in_grouped_h<<<dim3(NSLOT / GL_G, E_NUM), 256>>>(p_acth, A2, p_t2, H_DIM, 0);

    // 6. out = sum_k w_k * (a@W2^T + b2 + LSCALE * t2 @ B2[e]^T)  (fused, smem-staged)
    {
        dim3 grid(D_DIM / 128, NSLOT / 128);
        gemm2_combine_kernel<<<grid, 256, GSMEM>>>(p_acth, p_w2h, b2, B2, out, NSLOT, D_DIM, H_DIM);
    }
}

// round 17
// speedup vs baseline: 1.4652x; 1.0018x over previous
#include <cuda_runtime.h>
#include <cuda_fp16.h>
#include <math.h>
#include <stdint.h>

#define N_TOK 2048
#define D_DIM 1024
#define H_DIM 4096
#define E_NUM 8
#define R_DIM 16
#define LSCALE 2.0f
#define NSLOT (2*N_TOK)

// ---------------- scratch ----------------
__device__ __half g_acth[NSLOT * H_DIM];
__device__ float  g_t1[NSLOT * R_DIM];
__device__ float  g_t2[NSLOT * R_DIM];
__device__ int    g_sel[NSLOT];
__device__ float  g_wt[NSLOT];
__device__ int g_cnt[E_NUM];
__device__ int g_list[E_NUM * NSLOT];   // fixed per-expert regions
__device__ __half g_xh[N_TOK * D_DIM];
__device__ __half g_w1h[H_DIM * D_DIM];
__device__ __half g_w2h[D_DIM * H_DIM];

// ---------------- fused f32 -> f16 conversion of x, W1, W2 (one launch) ----------------
#define XCH (N_TOK * D_DIM / 8)
#define W1CH (H_DIM * D_DIM / 8)
__global__ void cvt_all(const float* __restrict__ x, const float* __restrict__ W1,
                        const float* __restrict__ W2) {
    if (blockIdx.x == 0 && threadIdx.x < E_NUM) g_cnt[threadIdx.x] = 0;
    int c = blockIdx.x * 256 + threadIdx.x;
    const float* in;
    __half* out;
    int lo;
    if (c < XCH) {
        in = x; lo = c;
        out = g_xh;
    } else if (c < XCH + W1CH) {
        in = W1; lo = c - XCH;
        out = g_w1h;
    } else {
        in = W2; lo = c - XCH - W1CH;
        out = g_w2h;
    }
    int i = lo * 8;
    float4 v0 = *(const float4*)(in + i);
    float4 v1 = *(const float4*)(in + i + 4);
    __half2 h[4];
    h[0] = __floats2half2_rn(v0.x, v0.y);
    h[1] = __floats2half2_rn(v0.z, v0.w);
    h[2] = __floats2half2_rn(v1.x, v1.y);
    h[3] = __floats2half2_rn(v1.z, v1.w);
    *(uint4*)(out + i) = *(uint4*)h;
}

// ---------------- router: 4 tokens/block, gate in smem, direct scatter ----------------
__global__ __launch_bounds__(256)
void router_kernel(const float* __restrict__ x, const float* __restrict__ gate) {
    __shared__ float gs[E_NUM * D_DIM];   // 32 KB
    __shared__ float lg[4][E_NUM];
    int tid = threadIdx.x, warp = tid >> 5, lane = tid & 31;
    for (int i = tid; i < E_NUM * D_DIM / 4; i += 256)
        ((float4*)gs)[i] = ((const float4*)gate)[i];
    __syncthreads();
    #pragma unroll
    for (int t = 0; t < 4; t++) {
        int tok = blockIdx.x * 4 + t;
        const float4* xr = (const float4*)(x + (size_t)tok * D_DIM);
        const float4* gr = (const float4*)(gs + warp * D_DIM);
        float s = 0.f;
        for (int i = lane; i < D_DIM / 4; i += 32) {
            float4 a = xr[i], b = gr[i];
            s += a.x * b.x + a.y * b.y + a.z * b.z + a.w * b.w;
        }
        #pragma unroll
        for (int o = 16; o; o >>= 1) s += __shfl_xor_sync(0xffffffffu, s, o);
        if (lane == 0) lg[t][warp] = s;
    }
    __syncthreads();
    if (tid < 4) {
        int tok = blockIdx.x * 4 + tid;
        float best = -1e30f; int i0 = 0;
        #pragma unroll
        for (int e = 0; e < E_NUM; e++) if (lg[tid][e] > best) { best = lg[tid][e]; i0 = e; }
        float best2 = -1e30f; int i1 = 0;
        #pragma unroll
        for (int e = 0; e < E_NUM; e++) if (e != i0 && lg[tid][e] > best2) { best2 = lg[tid][e]; i1 = e; }
        float p1 = expf(best2 - best);
        float inv = 1.f / (1.f + p1);
        g_sel[tok * 2 + 0] = i0; g_sel[tok * 2 + 1] = i1;
        g_wt[tok * 2 + 0] = inv; g_wt[tok * 2 + 1] = p1 * inv;
        int pos0 = atomicAdd(&g_cnt[i0], 1);
        g_list[i0 * NSLOT + pos0] = tok * 2;
        int pos1 = atomicAdd(&g_cnt[i1], 1);
        g_list[i1 * NSLOT + pos1] = tok * 2 + 1;
    }
}

// ---------------- GEMM machinery ----------------
__device__ __forceinline__ void mma_f16(float* c, const unsigned* a, const unsigned* b) {
    asm volatile(
        "mma.sync.aligned.m16n8k16.row.col.f32.f16.f16.f32 "
        "{%0,%1,%2,%3}, {%4,%5,%6,%7}, {%8,%9}, {%0,%1,%2,%3};"
        : "+f"(c[0]), "+f"(c[1]), "+f"(c[2]), "+f"(c[3])
        : "r"(a[0]), "r"(a[1]), "r"(a[2]), "r"(a[3]), "r"(b[0]), "r"(b[1]));
}
__device__ __forceinline__ void ldsm_x4(unsigned* r, uint32_t addr) {
    asm volatile("ldmatrix.sync.aligned.m8n8.x4.shared.b16 {%0,%1,%2,%3}, [%4];"
        : "=r"(r[0]), "=r"(r[1]), "=r"(r[2]), "=r"(r[3]) : "r"(addr));
}
__device__ __forceinline__ uint32_t smem_u32(const void* p) {
    uint32_t a;
    asm("{ .reg .u64 t; cvta.to.shared.u64 t, %1; cvt.u32.u64 %0, t; }" : "=r"(a) : "l"(p));
    return a;
}
__device__ __forceinline__ void cp_async16(uint32_t dst, const void* src) {
    asm volatile("cp.async.cg.shared.global [%0], [%1], 16;" :: "r"(dst), "l"(src));
}
#define CP_COMMIT() asm volatile("cp.async.commit_group;" ::: "memory")
#define CP_WAIT(n)  asm volatile("cp.async.wait_group %0;" :: "n"(n) : "memory")

#define GSTRH 40
#define GHTILE (128 * GSTRH)
#define GSTAGEB (2 * GHTILE * 2)
#define GSMEM (3 * GSTAGEB)

// common mainloop prelude macro (R11-identical)
#define GEMM_PRELUDE(A, B, K)                                                            \
    uint32_t sb = smem_u32(smh);                                                         \
    int bm = blockIdx.y * 128, bn = blockIdx.x * 128;                                    \
    int tid = threadIdx.x;                                                               \
    int lane = tid & 31, wid = tid >> 5;                                                 \
    int wm = (wid >> 1) * 32, wn = (wid & 1) * 64;                                       \
    int g = lane >> 2, tg = lane & 3;                                                    \
    int row0 = (tid * 2) >> 2,     q0 = (tid * 2) & 3;                                   \
    int row1 = (tid * 2 + 1) >> 2, q1 = (tid * 2 + 1) & 3;                               \
    const char* Ap0 = (const char*)(A + (size_t)(bm + row0) * K + q0 * 8);               \
    const char* Ap1 = (const char*)(A + (size_t)(bm + row1) * K + q1 * 8);               \
    const char* Bp0 = (const char*)(B + (size_t)(bn + row0) * K + q0 * 8);               \
    const char* Bp1 = (const char*)(B + (size_t)(bn + row1) * K + q1 * 8);               \
    uint32_t oA0 = (uint32_t)(row0 * GSTRH + q0 * 8) * 2;                                \
    uint32_t oA1 = (uint32_t)(row1 * GSTRH + q1 * 8) * 2;                                \
    uint32_t oB0 = (uint32_t)GHTILE * 2 + oA0;                                           \
    uint32_t oB1 = (uint32_t)GHTILE * 2 + oA1;                                           \
    uint32_t laA[2];                                                                     \
    _Pragma("unroll")                                                                    \
    for (int mt = 0; mt < 2; mt++)                                                       \
        laA[mt] = (uint32_t)((wm + mt * 16 + (lane & 15)) * GSTRH +                      \
                             ((lane & 16) ? 8 : 0)) * 2;                                 \
    uint32_t laB[4];                                                                     \
    _Pragma("unroll")                                                                    \
    for (int p = 0; p < 4; p++)                                                          \
        laB[p] = (uint32_t)GHTILE * 2 +                                                  \
                 (uint32_t)((wn + 16 * p + (lane & 7) + ((lane & 16) ? 8 : 0)) * GSTRH + \
                            ((lane & 8) ? 8 : 0)) * 2;                                   \
    float acc[2][8][4];                                                                  \
    _Pragma("unroll")                                                                    \
    for (int mt = 0; mt < 2; mt++)                                                       \
        _Pragma("unroll")                                                                \
        for (int nt = 0; nt < 8; nt++)                                                   \
            _Pragma("unroll")                                                            \
            for (int i = 0; i < 4; i++) acc[mt][nt][i] = 0.f;                            \
    int ntk = K >> 5;                                                                    \
    _Pragma("unroll")                                                                    \
    for (int s = 0; s < 2; s++) {                                                        \
        uint32_t st = sb + s * GSTAGEB;                                                  \
        size_t ko = (size_t)s * 64;                                                      \
        cp_async16(st + oA0, Ap0 + ko); cp_async16(st + oA1, Ap1 + ko);                  \
        cp_async16(st + oB0, Bp0 + ko); cp_async16(st + oB1, Bp1 + ko);                  \
        CP_COMMIT();                                                                     \
    }                                                                                    \
    for (int kt = 0; kt < ntk; kt++) {                                                   \
        int b = kt % 3;                                                                  \
        if (kt + 1 < ntk) { CP_WAIT(1); } else { CP_WAIT(0); }                           \
        __syncthreads();                                                                 \
        if (kt + 2 < ntk) {                                                              \
            int s = (kt + 2) % 3;                                                        \
            uint32_t st = sb + s * GSTAGEB;                                              \
            size_t ko = (size_t)(kt + 2) * 64;                                           \
            cp_async16(st + oA0, Ap0 + ko); cp_async16(st + oA1, Ap1 + ko);              \
            cp_async16(st + oB0, Bp0 + ko); cp_async16(st + oB1, Bp1 + ko);              \
            CP_COMMIT();                                                                 \
        }                                                                                \
        uint32_t stg = sb + b * GSTAGEB;                                                 \
        _Pragma("unroll")                                                                \
        for (int kg = 0; kg < 2; kg++) {                                                 \
            uint32_t kofs = kg * 32;                                                     \
            unsigned av[2][4], bv[4][4];                                                 \
            _Pragma("unroll")                                                            \
            for (int mt = 0; mt < 2; mt++)                                               \
                ldsm_x4(av[mt], stg + laA[mt] + kofs);                                   \
            _Pragma("unroll")                                                            \
            for (int p = 0; p < 4; p++)                                                  \
                ldsm_x4(bv[p], stg + laB[p] + kofs);                                     \
            _Pragma("unroll")                                                            \
            for (int mt = 0; mt < 2; mt++)                                               \
                _Pragma("unroll")                                                        \
                for (int nt = 0; nt < 8; nt++)                                           \
                    mma_f16(acc[mt][nt], av[mt], &bv[nt >> 1][(nt & 1) * 2]);            \
        }                                                                                \
    }

// smem-resident rank-16 dot: t (fp32[16]) . brow (fp16[16])
__device__ __forceinline__ float dot16h(const float* tv, const __half* brow) {
    const uint4* bp = (const uint4*)brow;
    uint4 u0 = bp[0], u1 = bp[1];
    const __half2* hp = (const __half2*)&u0;
    const __half2* hq = (const __half2*)&u1;
    float dot = 0.f;
    #pragma unroll
    for (int q = 0; q < 4; q++) {
        float2 f = __half22float2(hp[q]);
        dot += tv[q * 2] * f.x + tv[q * 2 + 1] * f.y;
    }
    #pragma unroll
    for (int q = 0; q < 4; q++) {
        float2 f = __half22float2(hq[q]);
        dot += tv[8 + q * 2] * f.x + tv[8 + q * 2 + 1] * f.y;
    }
    return dot;
}
__device__ __forceinline__ float fast_silu(float v) {
    return __fdividef(v, 1.f + __expf(-v));
}

// ---------------- GEMM1 + bias + LoRA-up + silu -> acth (smem-staged epilogue) ----------------
__global__ __launch_bounds__(256)
void gemm1_act_kernel(const __half* __restrict__ A, const __half* __restrict__ B,
                      const float* __restrict__ b1, const float* __restrict__ B1mat,
                      int M, int N, int K) {
    extern __shared__ __half smh[];
    GEMM_PRELUDE(A, B, K)

    __syncthreads();
    __half* B1s  = smh;                                   // 32768 B
    float*  t1s  = (float*)(smh + 16384);                 // 16384 B
    int*    sels = (int*)(smh + 16384 + 8192);            // 1024 B
    float*  b1s  = (float*)(smh + 16384 + 8192 + 512);    // 512 B

    for (int idx = tid; idx < E_NUM * 128; idx += 256) {
        int e = idx >> 7, hl = idx & 127;
        const float4* src = (const float4*)(B1mat + ((size_t)e * H_DIM + bn + hl) * R_DIM);
        float4 v0 = src[0], v1 = src[1], v2 = src[2], v3 = src[3];
        __half2 hv[8];
        hv[0] = __floats2half2_rn(v0.x, v0.y); hv[1] = __floats2half2_rn(v0.z, v0.w);
        hv[2] = __floats2half2_rn(v1.x, v1.y); hv[3] = __floats2half2_rn(v1.z, v1.w);
        hv[4] = __floats2half2_rn(v2.x, v2.y); hv[5] = __floats2half2_rn(v2.z, v2.w);
        hv[6] = __floats2half2_rn(v3.x, v3.y); hv[7] = __floats2half2_rn(v3.z, v3.w);
        uint4* dst = (uint4*)(B1s + idx * 16);
        dst[0] = ((uint4*)hv)[0];
        dst[1] = ((uint4*)hv)[1];
    }
    for (int idx = tid; idx < 1024; idx += 256)
        ((float4*)t1s)[idx] = *(const float4*)(g_t1 + (size_t)(2 * bm) * R_DIM + idx * 4);
    if (tid < 128) {
        b1s[tid] = b1[bn + tid];
    }
    for (int idx = tid; idx < 256; idx += 256)
        sels[idx] = g_sel[2 * bm + idx];
    __syncthreads();

    #pragma unroll
    for (int mt = 0; mt < 2; mt++) {
        #pragma unroll
        for (int rh = 0; rh < 2; rh++) {
            int lt = wm + mt * 16 + g + rh * 8;
            int lp0 = 2 * lt, lp1 = 2 * lt + 1;
            int e0 = sels[lp0], e1 = sels[lp1];
            const float* ta = t1s + lp0 * R_DIM;
            const float* tb = t1s + lp1 * R_DIM;
            __half* o0 = g_acth + (size_t)(2 * bm + lp0) * H_DIM + bn;
            __half* o1 = g_acth + (size_t)(2 * bm + lp1) * H_DIM + bn;
            #pragma unroll
            for (int nt = 0; nt < 8; nt++) {
                int c0 = wn + nt * 8 + 2 * tg;
                float a0[2], a1[2];
                #pragma unroll
                for (int j = 0; j < 2; j++) {
                    int hl = c0 + j;
                    float base = acc[mt][nt][rh * 2 + j] + b1s[hl];
                    float l0 = dot16h(ta, B1s + ((size_t)e0 * 128 + hl) * 16);
                    float l1 = dot16h(tb, B1s + ((size_t)e1 * 128 + hl) * 16);
                    a0[j] = fast_silu(base + LSCALE * l0);
                    a1[j] = fast_silu(base + LSCALE * l1);
                }
                *(__half2*)(o0 + c0) = __floats2half2_rn(a0[0], a0[1]);
                *(__half2*)(o1 + c0) = __floats2half2_rn(a1[0], a1[1]);
            }
        }
    }
}

// ---------------- GEMM2 + bias + LoRA-up + weighted combine (smem-staged epilogue) ----------------
__global__ __launch_bounds__(256)
void gemm2_combine_kernel(const __half* __restrict__ A, const __half* __restrict__ B,
                          const float* __restrict__ b2, const float* __restrict__ B2mat,
                          float* __restrict__ out, int M, int N, int K) {
    extern __shared__ __half smh[];
    GEMM_PRELUDE(A, B, K)

    __syncthreads();
    __half* B2s = smh;                               // 32KB
    float*  t2s = (float*)(smh + 16384);             // 8KB
    float*  wts = (float*)(smh + 16384 + 4096);      // [128]
    int*    sels = (int*)(smh + 16384 + 4096 + 256); // [128]
    float*  b2s = (float*)(smh + 16384 + 4096 + 512);// [128]

    for (int idx = tid; idx < E_NUM * 128; idx += 256) {
        int e = idx >> 7, dl = idx & 127;
        const float4* src = (const float4*)(B2mat + ((size_t)e * D_DIM + bn + dl) * R_DIM);
        float4 v0 = src[0], v1 = src[1], v2 = src[2], v3 = src[3];
        __half2 hv[8];
        hv[0] = __floats2half2_rn(v0.x, v0.y); hv[1] = __floats2half2_rn(v0.z, v0.w);
        hv[2] = __floats2half2_rn(v1.x, v1.y); hv[3] = __floats2half2_rn(v1.z, v1.w);
        hv[4] = __floats2half2_rn(v2.x, v2.y); hv[5] = __floats2half2_rn(v2.z, v2.w);
        hv[6] = __floats2half2_rn(v3.x, v3.y); hv[7] = __floats2half2_rn(v3.z, v3.w);
        uint4* dst = (uint4*)(B2s + idx * 16);
        dst[0] = ((uint4*)hv)[0];
        dst[1] = ((uint4*)hv)[1];
    }
    for (int idx = tid; idx < 512; idx += 256)
        ((float4*)t2s)[idx] = *(const float4*)(g_t2 + (size_t)bm * R_DIM + idx * 4);
    if (tid < 128) {
        wts[tid] = g_wt[bm + tid];
        sels[tid] = g_sel[bm + tid];
        b2s[tid] = b2[bn + tid];
    }
    __syncthreads();

    #pragma unroll
    for (int mt = 0; mt < 2; mt++) {
        #pragma unroll
        for (int rh = 0; rh < 2; rh++) {
            int lp = wm + mt * 16 + g + rh * 8;
            int e = sels[lp];
            float w = wts[lp];
            const float* tv = t2s + lp * R_DIM;
            float* orow = out + (size_t)((bm + lp) >> 1) * D_DIM;
            #pragma unroll
            for (int nt = 0; nt < 8; nt++) {
                int c0 = wn + nt * 8 + 2 * tg;
                float wv[2];
                #pragma unroll
                for (int j = 0; j < 2; j++) {
                    int dl = c0 + j;
                    float dot = dot16h(tv, B2s + ((size_t)e * 128 + dl) * 16);
                    wv[j] = w * (acc[mt][nt][rh * 2 + j] + b2s[dl] + LSCALE * dot);
                }
                float pv0 = __shfl_xor_sync(0xffffffffu, wv[0], 4);
                float pv1 = __shfl_xor_sync(0xffffffffu, wv[1], 4);
                if (!(g & 1))
                    *(float2*)(orow + bn + c0) = make_float2(wv[0] + pv0, wv[1] + pv1);
            }
        }
    }
}

// ---------------- grouped rank-16 down-projection (fp16 input rows, 16 slots/block) ----------------
#define GL_G 16
#define GL_SPW (GL_G / 8)     // slots per warp = 2
#define GL_KC 128
__global__ __launch_bounds__(256)
void lora_in_grouped_h(const __half* __restrict__ X, const float* __restrict__ Amat,
                       float* __restrict__ Tout, int K, int tok_row) {
    int e = blockIdx.y;
    int n_e = g_cnt[e];
    int base = blockIdx.x * GL_G;
    if (base >= n_e) return;
    __shared__ float As[R_DIM][GL_KC];
    __shared__ int sl[GL_G];
    int tid = threadIdx.x, lane = tid & 31, w = tid >> 5;
    if (tid < GL_G) {
        int j = base + tid;
        sl[tid] = (j < n_e) ? g_list[e * NSLOT + j] : -1;
    }
    __syncthreads();
    int p[GL_SPW];
    const __half* xr[GL_SPW];
    #pragma unroll
    for (int s = 0; s < GL_SPW; s++) {
        p[s] = sl[w * GL_SPW + s];
        int row = (p[s] < 0) ? 0 : (tok_row ? (p[s] >> 1) : p[s]);
        xr[s] = X + (size_t)row * K;
    }
    float acc[GL_SPW][R_DIM];
    #pragma unroll
    for (int s = 0; s < GL_SPW; s++)
        #pragma unroll
        for (int r = 0; r < R_DIM; r++) acc[s][r] = 0.f;

    const float* Ae = Amat + (size_t)e * R_DIM * K;
    for (int k0 = 0; k0 < K; k0 += GL_KC) {
        __syncthreads();
        #pragma unroll
        for (int l = 0; l < 2; l++) {
            int i = tid * 2 + l;
            int r = i >> 5, kq = i & 31;
            *(float4*)&As[r][kq * 4] = *(const float4*)(Ae + (size_t)r * K + k0 + kq * 4);
        }
        __syncthreads();
        float4 xv[GL_SPW];
        #pragma unroll
        for (int s = 0; s < GL_SPW; s++) {
            __half2 h01 = *(const __half2*)(xr[s] + k0 + lane * 4);
            __half2 h23 = *(const __half2*)(xr[s] + k0 + lane * 4 + 2);
            float2 f01 = __half22float2(h01);
            float2 f23 = __half22float2(h23);
            xv[s] = make_float4(f01.x, f01.y, f23.x, f23.y);
        }
        #pragma unroll
        for (int r = 0; r < R_DIM; r++) {
            float4 a4 = *(const float4*)&As[r][lane * 4];
            #pragma unroll
            for (int s = 0; s < GL_SPW; s++)
                acc[s][r] += xv[s].x * a4.x + xv[s].y * a4.y + xv[s].z * a4.z + xv[s].w * a4.w;
        }
    }
    #pragma unroll
    for (int s = 0; s < GL_SPW; s++) {
        #pragma unroll
        for (int r = 0; r < R_DIM; r++) {
            float v = acc[s][r];
            v += __shfl_xor_sync(0xffffffffu, v, 16);
            v += __shfl_xor_sync(0xffffffffu, v, 8);
            v += __shfl_xor_sync(0xffffffffu, v, 4);
            v += __shfl_xor_sync(0xffffffffu, v, 2);
            v += __shfl_xor_sync(0xffffffffu, v, 1);
            if (lane == 0 && p[s] >= 0) Tout[p[s] * R_DIM + r] = v;
        }
    }
}

// ---------------- launch ----------------
extern "C" void kernel_launch(void* const* d_in, const int* in_sizes, int n_in,
                              void* d_out, int out_size) {
    const float* x    = (const float*)d_in[0];
    const float* gate = (const float*)d_in[1];
    const float* W1   = (const float*)d_in[2];
    const float* b1   = (const float*)d_in[3];
    const float* W2   = (const float*)d_in[4];
    const float* b2   = (const float*)d_in[5];
    const float* A1   = (const float*)d_in[6];
    const float* B1   = (const float*)d_in[7];
    const float* A2   = (const float*)d_in[8];
    const float* B2   = (const float*)d_in[9];
    float* out = (float*)d_out;

    float *p_t1, *p_t2;
    __half *p_xh, *p_w1h, *p_w2h, *p_acth;
    cudaGetSymbolAddress((void**)&p_t1,   g_t1);
    cudaGetSymbolAddress((void**)&p_t2,   g_t2);
    cudaGetSymbolAddress((void**)&p_xh,   g_xh);
    cudaGetSymbolAddress((void**)&p_w1h,  g_w1h);
    cudaGetSymbolAddress((void**)&p_w2h,  g_w2h);
    cudaGetSymbolAddress((void**)&p_acth, g_acth);

    cudaFuncSetAttribute(gemm1_act_kernel,
                         cudaFuncAttributeMaxDynamicSharedMemorySize, GSMEM);
    cudaFuncSetAttribute(gemm2_combine_kernel,
                         cudaFuncAttributeMaxDynamicSharedMemorySize, GSMEM);

    // 0. fused fp16 conversion of x, W1, W2 (also zeroes expert counts)
    {
        int chunks = XCH + 2 * W1CH;
        cvt_all<<<chunks / 256, 256>>>(x, W1, W2);
    }

    // 1. router (smem gate, direct scatter into fixed per-expert regions)
    router_kernel<<<N_TOK / 4, 256>>>(x, gate);

    // 2. t1 = x @ A1[e]^T
    lora_in_grouped_h<<<dim3(NSLOT / GL_G, E_NUM), 256>>>(p_xh, A1, p_t1, D_DIM, 1);

    // 3. acth = silu(X@W1^T + b1 + LSCALE * t1 @ B1[e]^T)  (fused, smem-staged)
    {
        dim3 grid(H_DIM / 128, N_TOK / 128);
        gemm1_act_kernel<<<grid, 256, GSMEM>>>(p_xh, p_w1h, b1, B1, N_TOK, H_DIM, D_DIM);
    }

    // 4. t2 = a @ A2[e]^T
    lora_in_grouped_h<<<dim3(NSLOT / GL_G, E_NUM), 256>>>(p_acth, A2, p_t2, H_DIM, 0);

    // 5. out = sum_k w_k * (a@W2^T + b2 + LSCALE * t2 @ B2[e]^T)  (fused, smem-staged)
    {
        dim3 grid(D_DIM / 128, NSLOT / 128);
        gemm2_combine_kernel<<<grid, 256, GSMEM>>>(p_acth, p_w2h, b2, B2, out, NSLOT, D_DIM, H_DIM);
    }
}